// round 1
// baseline (speedup 1.0000x reference)
#include <cuda_runtime.h>

#define NB 16
#define NC 512
#define NHW 4096

// Scratch (device globals — no allocations allowed)
__device__ float g_q[(size_t)NB * 64 * NHW];          // 16.8 MB
__device__ float g_k[(size_t)NB * 64 * NHW];          // 16.8 MB
__device__ float g_v[(size_t)NB * NC * NHW];          // 134 MB
__device__ float g_attn[(size_t)NB * 8 * 64 * 64];    // 2 MB
__device__ float g_mid[(size_t)NB * NC * NHW];        // 134 MB

// ---------------------------------------------------------------------------
// Projection GEMM: out[b][o][hw] = sum_c W[o][c] * x[b][c][hw] + bias[o]
// Tile 64(M) x 64(N), BK=16, 256 threads, 4x4 per thread.
// OUT selects destination global (0=q, 1=k, 2=v).
// ---------------------------------------------------------------------------
template <int M, int OUT>
__global__ __launch_bounds__(256) void proj_kernel(const float* __restrict__ W,
                                                   const float* __restrict__ bias,
                                                   const float* __restrict__ x) {
    __shared__ __align__(16) float Ws[16][68];  // [kk][m], padded (bank + f4 align)
    __shared__ __align__(16) float Xs[16][64];  // [kk][n]

    const int n0 = blockIdx.x * 64;
    const int m0 = blockIdx.y * 64;
    const int b  = blockIdx.z;
    const float* xb = x + (size_t)b * NC * NHW;
    float* out = (OUT == 0) ? g_q : (OUT == 1) ? g_k : g_v;
    float* ob = out + (size_t)b * M * NHW;

    const int t  = threadIdx.x;
    const int tn = (t & 15) * 4;
    const int tm = (t >> 4) * 4;

    float acc[4][4] = {};

    for (int k0 = 0; k0 < NC; k0 += 16) {
#pragma unroll
        for (int i = 0; i < 4; i++) {
            int id = t + i * 256;                 // 1024 elems: 64m x 16k
            int kk = id & 15, mm = id >> 4;
            Ws[kk][mm] = W[(size_t)(m0 + mm) * NC + k0 + kk];
        }
#pragma unroll
        for (int i = 0; i < 4; i++) {
            int id = t + i * 256;                 // 1024 elems: 16k x 64n
            int kk = id >> 6, nn = id & 63;
            Xs[kk][nn] = xb[(size_t)(k0 + kk) * NHW + n0 + nn];
        }
        __syncthreads();

#pragma unroll
        for (int kk = 0; kk < 16; kk++) {
            float4 av = *reinterpret_cast<const float4*>(&Ws[kk][tm]);
            float4 bv = *reinterpret_cast<const float4*>(&Xs[kk][tn]);
            float a[4] = {av.x, av.y, av.z, av.w};
            float bb[4] = {bv.x, bv.y, bv.z, bv.w};
#pragma unroll
            for (int i = 0; i < 4; i++)
#pragma unroll
                for (int j = 0; j < 4; j++)
                    acc[i][j] = fmaf(a[i], bb[j], acc[i][j]);
        }
        __syncthreads();
    }

#pragma unroll
    for (int i = 0; i < 4; i++) {
        float bvv = bias[m0 + tm + i];
        float4 r = make_float4(acc[i][0] + bvv, acc[i][1] + bvv,
                               acc[i][2] + bvv, acc[i][3] + bvv);
        *reinterpret_cast<float4*>(&ob[(size_t)(m0 + tm + i) * NHW + n0 + tn]) = r;
    }
}

// ---------------------------------------------------------------------------
// Scores + softmax per (b, head):
//   S[d][e] = (1/8) * sum_l q_t[b,n,d,l] * k_t[b,n,e,l],  softmax over e.
//   q_t[b,n,d,l] = g_q[b*262144 + n*32768 + l*64 + d]  (each 64-l chunk = one
//   contiguous 4096-float channel slab).
// One block per (b,n): 128 blocks, 256 threads, 4x4 per thread on 64x64 S.
// ---------------------------------------------------------------------------
__global__ __launch_bounds__(256) void scores_kernel() {
    const int bn = blockIdx.x;
    const int b = bn >> 3, n = bn & 7;
    const float* qb = g_q + (size_t)b * 64 * NHW + (size_t)n * 32768;
    const float* kb = g_k + (size_t)b * 64 * NHW + (size_t)n * 32768;

    __shared__ float Qs[64][65];
    __shared__ float Ks[64][65];

    const int t  = threadIdx.x;
    const int te = (t & 15) * 4;
    const int td = (t >> 4) * 4;

    float acc[4][4] = {};

    for (int lc = 0; lc < 8; lc++) {
#pragma unroll
        for (int i = 0; i < 16; i++) {
            int id = t + i * 256;                 // 4096 elems
            Qs[id >> 6][id & 63] = qb[lc * 4096 + id];
            Ks[id >> 6][id & 63] = kb[lc * 4096 + id];
        }
        __syncthreads();
#pragma unroll 8
        for (int li = 0; li < 64; li++) {
            float a[4], bb[4];
#pragma unroll
            for (int i = 0; i < 4; i++) a[i] = Qs[li][td + i];
#pragma unroll
            for (int j = 0; j < 4; j++) bb[j] = Ks[li][te + j];
#pragma unroll
            for (int i = 0; i < 4; i++)
#pragma unroll
                for (int j = 0; j < 4; j++)
                    acc[i][j] = fmaf(a[i], bb[j], acc[i][j]);
        }
        __syncthreads();
    }

    // Stage scores into Qs and softmax rows (over e).
#pragma unroll
    for (int i = 0; i < 4; i++)
#pragma unroll
        for (int j = 0; j < 4; j++)
            Qs[td + i][te + j] = acc[i][j] * 0.125f;   // 1/sqrt(64)
    __syncthreads();

    if (t < 64) {
        float m = -1e30f;
        for (int e = 0; e < 64; e++) m = fmaxf(m, Qs[t][e]);
        float s = 0.f;
        for (int e = 0; e < 64; e++) {
            float v2 = __expf(Qs[t][e] - m);
            Qs[t][e] = v2;
            s += v2;
        }
        float inv = 1.f / s;
        for (int e = 0; e < 64; e++) Qs[t][e] *= inv;
    }
    __syncthreads();

    float* ab = g_attn + (size_t)bn * 4096;
#pragma unroll
    for (int i = 0; i < 16; i++) {
        int id = t + i * 256;
        ab[id] = Qs[id >> 6][id & 63];
    }
}

// ---------------------------------------------------------------------------
// attn @ v, with output scramble folded in:
//   out_mid[b, ch=d2*8+n, h, w] = sum_e attn[b,n,w,e] * v[b, c=n*64+d2, h*64+e]
// One block per (b, v-channel c): 8192 blocks of 64x64x64.
// ---------------------------------------------------------------------------
__global__ __launch_bounds__(256) void attnv_kernel() {
    const int c = blockIdx.x;      // v channel = n*64 + d2
    const int b = blockIdx.y;
    const int n = c >> 6, d2 = c & 63;
    const float* vb = g_v + ((size_t)b * NC + c) * NHW;          // [64h][64e]
    const float* ab = g_attn + ((size_t)b * 8 + n) * 4096;       // A[w][e]

    __shared__ float Vs[64][65];
    __shared__ float As[64][65];

    const int t  = threadIdx.x;
    const int tw = (t & 15) * 4;
    const int th = (t >> 4) * 4;

#pragma unroll
    for (int i = 0; i < 16; i++) {
        int id = t + i * 256;
        Vs[id >> 6][id & 63] = vb[id];
        As[id >> 6][id & 63] = ab[id];
    }
    __syncthreads();

    float acc[4][4] = {};
#pragma unroll 8
    for (int e = 0; e < 64; e++) {
        float a[4], bb[4];
#pragma unroll
        for (int i = 0; i < 4; i++) a[i] = Vs[th + i][e];
#pragma unroll
        for (int j = 0; j < 4; j++) bb[j] = As[tw + j][e];
#pragma unroll
        for (int i = 0; i < 4; i++)
#pragma unroll
            for (int j = 0; j < 4; j++)
                acc[i][j] = fmaf(a[i], bb[j], acc[i][j]);
    }

    const int ch = d2 * 8 + n;
    float* ob = g_mid + ((size_t)b * NC + ch) * NHW;
#pragma unroll
    for (int i = 0; i < 4; i++) {
        float4 r = make_float4(acc[i][0], acc[i][1], acc[i][2], acc[i][3]);
        *reinterpret_cast<float4*>(&ob[(th + i) * 64 + tw]) = r;
    }
}

// ---------------------------------------------------------------------------
// Final linear on the reinterpreted flat view:
//   Y[b][r][o] = sum_c mid_flat[b][r*512+c] * Wo[o][c] + bo[o]
// written flat (== the torch double-reshape). Per-b GEMM [4096,512]x[512,512].
// ---------------------------------------------------------------------------
__global__ __launch_bounds__(256) void final_kernel(const float* __restrict__ Wo,
                                                    const float* __restrict__ bo,
                                                    float* __restrict__ out) {
    __shared__ __align__(16) float Ms[16][68];  // [kk][r]
    __shared__ __align__(16) float Ns[16][68];  // [kk][o]

    const int o0 = blockIdx.x * 64;
    const int r0 = blockIdx.y * 64;
    const int b  = blockIdx.z;
    const float* mb = g_mid + (size_t)b * NC * NHW;
    float* ob = out + (size_t)b * NC * NHW;

    const int t  = threadIdx.x;
    const int to = (t & 15) * 4;
    const int tr = (t >> 4) * 4;

    float acc[4][4] = {};

    for (int k0 = 0; k0 < NC; k0 += 16) {
#pragma unroll
        for (int i = 0; i < 4; i++) {
            int id = t + i * 256;
            int kk = id & 15, rr = id >> 4;
            Ms[kk][rr] = mb[(size_t)(r0 + rr) * NC + k0 + kk];
            Ns[kk][rr] = Wo[(size_t)(o0 + rr) * NC + k0 + kk];
        }
        __syncthreads();
#pragma unroll
        for (int kk = 0; kk < 16; kk++) {
            float4 av = *reinterpret_cast<const float4*>(&Ms[kk][tr]);
            float4 bv = *reinterpret_cast<const float4*>(&Ns[kk][to]);
            float a[4] = {av.x, av.y, av.z, av.w};
            float bb[4] = {bv.x, bv.y, bv.z, bv.w};
#pragma unroll
            for (int i = 0; i < 4; i++)
#pragma unroll
                for (int j = 0; j < 4; j++)
                    acc[i][j] = fmaf(a[i], bb[j], acc[i][j]);
        }
        __syncthreads();
    }

#pragma unroll
    for (int i = 0; i < 4; i++) {
#pragma unroll
        for (int j = 0; j < 4; j++)
            ob[(size_t)(r0 + tr + i) * NC + o0 + to + j] = acc[i][j] + bo[o0 + to + j];
    }
}

// ---------------------------------------------------------------------------
extern "C" void kernel_launch(void* const* d_in, const int* in_sizes, int n_in,
                              void* d_out, int out_size) {
    (void)in_sizes; (void)n_in; (void)out_size;
    const float* x  = (const float*)d_in[0];
    const float* Wq = (const float*)d_in[1];
    const float* bq = (const float*)d_in[2];
    const float* Wk = (const float*)d_in[3];
    const float* bk = (const float*)d_in[4];
    const float* Wv = (const float*)d_in[5];
    const float* bv = (const float*)d_in[6];
    const float* Wo = (const float*)d_in[7];
    const float* bo = (const float*)d_in[8];
    float* out = (float*)d_out;

    proj_kernel<64, 0><<<dim3(NHW / 64, 1, NB), 256>>>(Wq, bq, x);
    proj_kernel<64, 1><<<dim3(NHW / 64, 1, NB), 256>>>(Wk, bk, x);
    proj_kernel<512, 2><<<dim3(NHW / 64, 8, NB), 256>>>(Wv, bv, x);
    scores_kernel<<<128, 256>>>();
    attnv_kernel<<<dim3(512, NB), 256>>>();
    final_kernel<<<dim3(8, 64, NB), 256>>>(Wo, bo, out);
}

// round 2
// speedup vs baseline: 2.7337x; 2.7337x over previous
#include <cuda_runtime.h>
#include <cstdint>

#define NB 16
#define NC 512
#define NHW 4096

// Scratch (device globals — no allocations allowed)
__device__ float g_qk[(size_t)NB * 128 * NHW];        // q rows 0-63, k rows 64-127
__device__ float g_v[(size_t)NB * NC * NHW];
__device__ float g_attn[(size_t)NB * 8 * 64 * 64];
__device__ float g_mid[(size_t)NB * NC * NHW];
__device__ float g_Wqk[128 * NC];
__device__ float g_bqk[128];

__device__ __forceinline__ uint32_t f2tf(float f) {
    uint32_t o; asm("cvt.rna.tf32.f32 %0, %1;" : "=r"(o) : "f"(f)); return o;
}

// ---------------------------------------------------------------------------
// tf32 tensor-core GEMM, 128x128 block tile, BK=32, 8 warps (warp tile 32x64).
// C[m][n] = sum_k A[m][k]*B(k,n) + bias.
//   BT=false: B element (k,n) at B[k*ldb + n]   (proj: B = x),  bias over m
//   BT=true:  B element (k,n) at B[n*ldb + k]   (final: B = Wo), bias over n
// K = NC = 512 fixed. All dims divide tiles exactly.
// ---------------------------------------------------------------------------
template <bool BT>
__global__ __launch_bounds__(256) void gemm_tf32(
    const float* __restrict__ A, size_t sAb, int lda,
    const float* __restrict__ B, size_t sBb, int ldb,
    const float* __restrict__ bias,
    float* __restrict__ C, size_t sCb, int ldc)
{
    __shared__ uint32_t As[128][36];   // [m][k], pad -> conflict-free frag reads
    __shared__ uint32_t Bs[32][136];   // [k][n], pad 8 -> conflict-free frag reads

    const int b  = blockIdx.z;
    const int n0 = blockIdx.x * 128;
    const int m0 = blockIdx.y * 128;
    A += (size_t)b * sAb; B += (size_t)b * sBb; C += (size_t)b * sCb;

    const int t = threadIdx.x, lane = t & 31, w = t >> 5;
    const int wm = (w & 3) * 32;   // warp row base in tile
    const int wn = (w >> 2) * 64;  // warp col base in tile

    float acc[2][8][4] = {};

    for (int ko = 0; ko < NC; ko += 32) {
        // A tile: 128m x 32k, row-major k-contig, float4 loads
#pragma unroll
        for (int i = 0; i < 4; i++) {
            int id = t + i * 256;
            int r = id >> 3, k4 = (id & 7) * 4;
            float4 v = *reinterpret_cast<const float4*>(&A[(size_t)(m0 + r) * lda + ko + k4]);
            As[r][k4]     = f2tf(v.x); As[r][k4 + 1] = f2tf(v.y);
            As[r][k4 + 2] = f2tf(v.z); As[r][k4 + 3] = f2tf(v.w);
        }
        // B tile: 32k x 128n
        if (!BT) {
#pragma unroll
            for (int i = 0; i < 4; i++) {
                int id = t + i * 256;
                int k = id >> 5, n4 = (id & 31) * 4;
                float4 v = *reinterpret_cast<const float4*>(&B[(size_t)(ko + k) * ldb + n0 + n4]);
                Bs[k][n4]     = f2tf(v.x); Bs[k][n4 + 1] = f2tf(v.y);
                Bs[k][n4 + 2] = f2tf(v.z); Bs[k][n4 + 3] = f2tf(v.w);
            }
        } else {
#pragma unroll
            for (int i = 0; i < 4; i++) {
                int id = t + i * 256;
                int n = id >> 3, k4 = (id & 7) * 4;
                float4 v = *reinterpret_cast<const float4*>(&B[(size_t)(n0 + n) * ldb + ko + k4]);
                Bs[k4][n]     = f2tf(v.x); Bs[k4 + 1][n] = f2tf(v.y);
                Bs[k4 + 2][n] = f2tf(v.z); Bs[k4 + 3][n] = f2tf(v.w);
            }
        }
        __syncthreads();

#pragma unroll
        for (int kk = 0; kk < 4; kk++) {
            const int k8 = kk * 8;
            uint32_t af[2][4];
#pragma unroll
            for (int mi = 0; mi < 2; mi++) {
                int rb = wm + mi * 16 + (lane >> 2);
                int cb = k8 + (lane & 3);
                af[mi][0] = As[rb][cb];     af[mi][1] = As[rb + 8][cb];
                af[mi][2] = As[rb][cb + 4]; af[mi][3] = As[rb + 8][cb + 4];
            }
#pragma unroll
            for (int ni = 0; ni < 8; ni++) {
                int nb = wn + ni * 8 + (lane >> 2);
                int kb = k8 + (lane & 3);
                uint32_t b0 = Bs[kb][nb], b1 = Bs[kb + 4][nb];
#pragma unroll
                for (int mi = 0; mi < 2; mi++) {
                    asm volatile(
                        "mma.sync.aligned.m16n8k8.row.col.f32.tf32.tf32.f32 "
                        "{%0,%1,%2,%3},{%4,%5,%6,%7},{%8,%9},{%0,%1,%2,%3};"
                        : "+f"(acc[mi][ni][0]), "+f"(acc[mi][ni][1]),
                          "+f"(acc[mi][ni][2]), "+f"(acc[mi][ni][3])
                        : "r"(af[mi][0]), "r"(af[mi][1]), "r"(af[mi][2]), "r"(af[mi][3]),
                          "r"(b0), "r"(b1));
                }
            }
        }
        __syncthreads();
    }

    // Epilogue: c0/c1 at (row, 2c), (row, 2c+1); c2/c3 at row+8.
#pragma unroll
    for (int mi = 0; mi < 2; mi++) {
        int r0 = m0 + wm + mi * 16 + (lane >> 2);
#pragma unroll
        for (int ni = 0; ni < 8; ni++) {
            int c0 = n0 + wn + ni * 8 + (lane & 3) * 2;
#pragma unroll
            for (int rr = 0; rr < 2; rr++) {
                int r = r0 + rr * 8;
                float v0 = acc[mi][ni][rr * 2], v1 = acc[mi][ni][rr * 2 + 1];
                if (BT) { v0 += bias[c0]; v1 += bias[c0 + 1]; }
                else    { float bv = bias[r]; v0 += bv; v1 += bv; }
                *reinterpret_cast<float2*>(&C[(size_t)r * ldc + c0]) = make_float2(v0, v1);
            }
        }
    }
}

// ---------------------------------------------------------------------------
// Pack Wq/Wk -> g_Wqk[128][512], bq/bk -> g_bqk[128]
// ---------------------------------------------------------------------------
__global__ void pack_qk(const float* __restrict__ Wq, const float* __restrict__ bq,
                        const float* __restrict__ Wk, const float* __restrict__ bk) {
    int i = blockIdx.x * 256 + threadIdx.x;
    if (i < 64 * NC) { g_Wqk[i] = Wq[i]; g_Wqk[64 * NC + i] = Wk[i]; }
    if (i < 64) { g_bqk[i] = bq[i]; g_bqk[64 + i] = bk[i]; }
}

// ---------------------------------------------------------------------------
// Scores + softmax per (b, head). q = g_qk rows 0-63, k = rows 64-127.
//   S[d][e] = (1/8) * sum_l q_t[d,l] k_t[e,l];  q_t[n,d,l] at n*32768 + l*64 + d
// ---------------------------------------------------------------------------
__global__ __launch_bounds__(256) void scores_kernel() {
    const int bn = blockIdx.x;
    const int b = bn >> 3, n = bn & 7;
    const float* qb = g_qk + (size_t)b * 128 * NHW + (size_t)n * 32768;
    const float* kb = qb + 64 * NHW;

    __shared__ float Qs[64][65];
    __shared__ float Ks[64][65];

    const int t  = threadIdx.x;
    const int te = (t & 15) * 4;
    const int td = (t >> 4) * 4;

    float acc[4][4] = {};

    for (int lc = 0; lc < 8; lc++) {
#pragma unroll
        for (int i = 0; i < 16; i++) {
            int id = t + i * 256;
            Qs[id >> 6][id & 63] = qb[lc * 4096 + id];
            Ks[id >> 6][id & 63] = kb[lc * 4096 + id];
        }
        __syncthreads();
#pragma unroll 8
        for (int li = 0; li < 64; li++) {
            float a[4], bb[4];
#pragma unroll
            for (int i = 0; i < 4; i++) a[i] = Qs[li][td + i];
#pragma unroll
            for (int j = 0; j < 4; j++) bb[j] = Ks[li][te + j];
#pragma unroll
            for (int i = 0; i < 4; i++)
#pragma unroll
                for (int j = 0; j < 4; j++)
                    acc[i][j] = fmaf(a[i], bb[j], acc[i][j]);
        }
        __syncthreads();
    }

#pragma unroll
    for (int i = 0; i < 4; i++)
#pragma unroll
        for (int j = 0; j < 4; j++)
            Qs[td + i][te + j] = acc[i][j] * 0.125f;
    __syncthreads();

    if (t < 64) {
        float m = -1e30f;
        for (int e = 0; e < 64; e++) m = fmaxf(m, Qs[t][e]);
        float s = 0.f;
        for (int e = 0; e < 64; e++) { float v2 = __expf(Qs[t][e] - m); Qs[t][e] = v2; s += v2; }
        float inv = 1.f / s;
        for (int e = 0; e < 64; e++) Qs[t][e] *= inv;
    }
    __syncthreads();

    float* ab = g_attn + (size_t)bn * 4096;
#pragma unroll
    for (int i = 0; i < 16; i++) {
        int id = t + i * 256;
        ab[id] = Qs[id >> 6][id & 63];
    }
}

// ---------------------------------------------------------------------------
// attn @ v with output scramble folded in:
//   g_mid[b, ch=d2*8+n, h, w] = sum_e attn[b,n,w,e] * v[b, c=n*64+d2, h*64+e]
// ---------------------------------------------------------------------------
__global__ __launch_bounds__(256) void attnv_kernel() {
    const int c = blockIdx.x;
    const int b = blockIdx.y;
    const int n = c >> 6, d2 = c & 63;
    const float* vb = g_v + ((size_t)b * NC + c) * NHW;
    const float* ab = g_attn + ((size_t)b * 8 + n) * 4096;

    __shared__ float Vs[64][65];
    __shared__ float As2[64][65];

    const int t  = threadIdx.x;
    const int tw = (t & 15) * 4;
    const int th = (t >> 4) * 4;

#pragma unroll
    for (int i = 0; i < 16; i++) {
        int id = t + i * 256;
        Vs[id >> 6][id & 63] = vb[id];
        As2[id >> 6][id & 63] = ab[id];
    }
    __syncthreads();

    float acc[4][4] = {};
#pragma unroll 8
    for (int e = 0; e < 64; e++) {
        float a[4], bb[4];
#pragma unroll
        for (int i = 0; i < 4; i++) a[i] = Vs[th + i][e];
#pragma unroll
        for (int j = 0; j < 4; j++) bb[j] = As2[tw + j][e];
#pragma unroll
        for (int i = 0; i < 4; i++)
#pragma unroll
            for (int j = 0; j < 4; j++)
                acc[i][j] = fmaf(a[i], bb[j], acc[i][j]);
    }

    const int ch = d2 * 8 + n;
    float* ob = g_mid + ((size_t)b * NC + ch) * NHW;
#pragma unroll
    for (int i = 0; i < 4; i++) {
        float4 r = make_float4(acc[i][0], acc[i][1], acc[i][2], acc[i][3]);
        *reinterpret_cast<float4*>(&ob[(th + i) * 64 + tw]) = r;
    }
}

// ---------------------------------------------------------------------------
extern "C" void kernel_launch(void* const* d_in, const int* in_sizes, int n_in,
                              void* d_out, int out_size) {
    (void)in_sizes; (void)n_in; (void)out_size;
    const float* x  = (const float*)d_in[0];
    const float* Wq = (const float*)d_in[1];
    const float* bq = (const float*)d_in[2];
    const float* Wk = (const float*)d_in[3];
    const float* bk = (const float*)d_in[4];
    const float* Wv = (const float*)d_in[5];
    const float* bv = (const float*)d_in[6];
    const float* Wo = (const float*)d_in[7];
    const float* bo = (const float*)d_in[8];
    float* out = (float*)d_out;

    pack_qk<<<128, 256>>>(Wq, bq, Wk, bk);

    float *g_qk_p, *g_v_p, *g_mid_p, *g_Wqk_p, *g_bqk_p;
    cudaGetSymbolAddress((void**)&g_qk_p, g_qk);
    cudaGetSymbolAddress((void**)&g_v_p, g_v);
    cudaGetSymbolAddress((void**)&g_mid_p, g_mid);
    cudaGetSymbolAddress((void**)&g_Wqk_p, g_Wqk);
    cudaGetSymbolAddress((void**)&g_bqk_p, g_bqk);

    // q/k projection: C[128 x 4096] per b
    gemm_tf32<false><<<dim3(32, 1, NB), 256>>>(
        g_Wqk_p, 0, NC, x, (size_t)NC * NHW, NHW, g_bqk_p,
        g_qk_p, (size_t)128 * NHW, NHW);
    // v projection: C[512 x 4096] per b
    gemm_tf32<false><<<dim3(32, 4, NB), 256>>>(
        Wv, 0, NC, x, (size_t)NC * NHW, NHW, bv,
        g_v_p, (size_t)NC * NHW, NHW);

    scores_kernel<<<128, 256>>>();
    attnv_kernel<<<dim3(512, NB), 256>>>();

    // final linear: Y[4096 x 512] per b, B = Wo[o][c] (BT layout), bias over n
    gemm_tf32<true><<<dim3(4, 32, NB), 256>>>(
        g_mid_p, (size_t)NC * NHW, NC, Wo, 0, NC, bo,
        out, (size_t)NC * NHW, NC);
}

// round 4
// speedup vs baseline: 3.0100x; 1.1011x over previous
#include <cuda_runtime.h>
#include <cuda_bf16.h>
#include <cstdint>

#define NB 16
#define NC 512
#define NHW 4096
#define KDIM 512

// ---------------------------------------------------------------- scratch
__device__ float g_x32[(size_t)NB * NC * NHW];   // tf32-rounded x
__device__ float g_qk[(size_t)NB * 128 * NHW];
__device__ float g_v[(size_t)NB * NC * NHW];
__device__ float g_attn[(size_t)NB * 8 * 64 * 64];
__device__ float g_mid[(size_t)NB * NC * NHW];   // tf32-rounded mid
__device__ float g_Wqk[128 * NC];                // tf32-rounded, q rows 0-63, k 64-127
__device__ float g_Wv32[NC * NC];
__device__ float g_Wo32[NC * NC];
__device__ float g_bqk[128];

__device__ __forceinline__ float f2tf(float f) {
    uint32_t o; asm("cvt.rna.tf32.f32 %0, %1;" : "=r"(o) : "f"(f));
    return __uint_as_float(o);
}

#define CP16(dst, src) asm volatile("cp.async.cg.shared.global [%0], [%1], 16;" :: "r"(dst), "l"(src) : "memory")
#define CP_COMMIT()    asm volatile("cp.async.commit_group;" ::: "memory")
#define CP_WAIT1()     asm volatile("cp.async.wait_group 1;" ::: "memory")
#define CP_WAIT0()     asm volatile("cp.async.wait_group 0;" ::: "memory")

__device__ __forceinline__ uint32_t smem_u32(const void* p) {
    uint32_t a;
    asm("{ .reg .u64 t; cvta.to.shared.u64 t, %1; cvt.u32.u64 %0, t; }" : "=r"(a) : "l"(p));
    return a;
}

// ---------------------------------------------------------------------------
// tf32 mma.sync GEMM, 128x128 tile, BK=32, double-buffered cp.async.
// Operands are PRE-ROUNDED to tf32 (low mantissa bits zero) -> no cvt in loop.
// C[m][n] = sum_k A[m][k]*B(k,n) + bias.
//   A: [m][k] k-contig (lda).
//   BT=false: B (k,n) at B[k*ldb + n] (n-contig), bias over m.
//   BT=true:  B (k,n) at B[n*ldb + k] (k-contig), bias over n.
// K = 512. 8 warps, warp tile 32x64 (m16n8k8, 2x8 mma grid, 4 k-steps/iter).
// ---------------------------------------------------------------------------
#define A_BUF 4608            // 128*36 floats per buffer
#define BN_BUF 4224           // 32*132 floats (BT=false)
#define BT_BUF 4608           // 128*36 floats (BT=true)
#define SMEM_FLOATS (2 * A_BUF + 2 * 4608)
#define SMEM_BYTES (SMEM_FLOATS * 4)

template <bool BT>
__global__ __launch_bounds__(256, 2) void gemm_tf32(
    const float* __restrict__ A, size_t sAb, int lda,
    const float* __restrict__ B, size_t sBb, int ldb,
    const float* __restrict__ bias,
    float* __restrict__ C, size_t sCb, int ldc)
{
    extern __shared__ __align__(16) float sm[];
    float* As = sm;                 // [2][128][36]
    float* Bs = sm + 2 * A_BUF;     // [2][32][132] or [2][128][36]
    const uint32_t sA = smem_u32(As), sB = smem_u32(Bs);

    const int b  = blockIdx.z;
    const int n0 = blockIdx.x * 128;
    const int m0 = blockIdx.y * 128;
    const float* Ap = A + (size_t)b * sAb + (size_t)m0 * lda;
    const float* Bp = B + (size_t)b * sBb;

    const int t = threadIdx.x, lane = t & 31, w = t >> 5;
    const int wm = (w & 3) * 32;
    const int wn = (w >> 2) * 64;
    const int q = lane >> 2, s = lane & 3;

    float acc[2][8][4] = {};

    auto ld_tiles = [&](int buf, int ko) {
#pragma unroll
        for (int i = 0; i < 4; i++) {
            int id = t + i * 256;
            int r = id >> 3, c4 = (id & 7) * 4;
            CP16(sA + (uint32_t)(buf * A_BUF + r * 36 + c4) * 4,
                 Ap + (size_t)r * lda + ko + c4);
        }
        if (!BT) {
#pragma unroll
            for (int i = 0; i < 4; i++) {
                int id = t + i * 256;
                int k = id >> 5, n4 = (id & 31) * 4;
                CP16(sB + (uint32_t)(buf * BN_BUF + k * 132 + n4) * 4,
                     Bp + (size_t)(ko + k) * ldb + n0 + n4);
            }
        } else {
#pragma unroll
            for (int i = 0; i < 4; i++) {
                int id = t + i * 256;
                int n = id >> 3, c4 = (id & 7) * 4;
                CP16(sB + (uint32_t)(buf * BT_BUF + n * 36 + c4) * 4,
                     Bp + (size_t)(n0 + n) * ldb + ko + c4);
            }
        }
        CP_COMMIT();
    };

    ld_tiles(0, 0);

    const int NIT = KDIM / 32;
    for (int it = 0; it < NIT; it++) {
        const int buf = it & 1;
        if (it < NIT - 1) { ld_tiles(buf ^ 1, (it + 1) * 32); CP_WAIT1(); }
        else              { CP_WAIT0(); }
        __syncthreads();

        const float* Ab = As + buf * A_BUF;
        const float* Bb = Bs + buf * (BT ? BT_BUF : BN_BUF);
#pragma unroll
        for (int kk = 0; kk < 4; kk++) {
            const int k8 = kk * 8;
            uint32_t af[2][4];
#pragma unroll
            for (int mi = 0; mi < 2; mi++) {
                const int rb = wm + mi * 16 + q, cb = k8 + s;
                af[mi][0] = __float_as_uint(Ab[rb * 36 + cb]);
                af[mi][1] = __float_as_uint(Ab[(rb + 8) * 36 + cb]);
                af[mi][2] = __float_as_uint(Ab[rb * 36 + cb + 4]);
                af[mi][3] = __float_as_uint(Ab[(rb + 8) * 36 + cb + 4]);
            }
#pragma unroll
            for (int ni = 0; ni < 8; ni++) {
                const int nb = wn + ni * 8 + q;
                uint32_t b0, b1;
                if (!BT) {
                    b0 = __float_as_uint(Bb[(k8 + s) * 132 + nb]);
                    b1 = __float_as_uint(Bb[(k8 + 4 + s) * 132 + nb]);
                } else {
                    b0 = __float_as_uint(Bb[nb * 36 + k8 + s]);
                    b1 = __float_as_uint(Bb[nb * 36 + k8 + 4 + s]);
                }
#pragma unroll
                for (int mi = 0; mi < 2; mi++) {
                    asm volatile(
                        "mma.sync.aligned.m16n8k8.row.col.f32.tf32.tf32.f32 "
                        "{%0,%1,%2,%3},{%4,%5,%6,%7},{%8,%9},{%0,%1,%2,%3};"
                        : "+f"(acc[mi][ni][0]), "+f"(acc[mi][ni][1]),
                          "+f"(acc[mi][ni][2]), "+f"(acc[mi][ni][3])
                        : "r"(af[mi][0]), "r"(af[mi][1]), "r"(af[mi][2]), "r"(af[mi][3]),
                          "r"(b0), "r"(b1));
                }
            }
        }
        __syncthreads();
    }

    float* Cp = C + (size_t)b * sCb;
#pragma unroll
    for (int mi = 0; mi < 2; mi++) {
        int r0 = m0 + wm + mi * 16 + q;
#pragma unroll
        for (int ni = 0; ni < 8; ni++) {
            int c0 = n0 + wn + ni * 8 + s * 2;
#pragma unroll
            for (int rr = 0; rr < 2; rr++) {
                int r = r0 + rr * 8;
                float v0 = acc[mi][ni][rr * 2], v1 = acc[mi][ni][rr * 2 + 1];
                if (BT) { v0 += bias[c0]; v1 += bias[c0 + 1]; }
                else    { float bv = bias[r]; v0 += bv; v1 += bv; }
                *reinterpret_cast<float2*>(&Cp[(size_t)r * ldc + c0]) = make_float2(v0, v1);
            }
        }
    }
}

// ---------------------------------------------------------------- pre-passes
__global__ void round_w(const float* __restrict__ Wq, const float* __restrict__ bq,
                        const float* __restrict__ Wk, const float* __restrict__ bk,
                        const float* __restrict__ Wv, const float* __restrict__ Wo) {
    int idx = blockIdx.x * 256 + threadIdx.x;
    int job = blockIdx.y;
    if (job == 0) {
        if (idx < NC * NC) g_Wv32[idx] = f2tf(Wv[idx]);
    } else if (job == 1) {
        if (idx < NC * NC) g_Wo32[idx] = f2tf(Wo[idx]);
    } else {
        if (idx < 64 * NC) {
            g_Wqk[idx] = f2tf(Wq[idx]);
            g_Wqk[64 * NC + idx] = f2tf(Wk[idx]);
        }
        if (idx < 64) { g_bqk[idx] = bq[idx]; g_bqk[64 + idx] = bk[idx]; }
    }
}

__global__ __launch_bounds__(256) void round_x(const float4* __restrict__ x) {
    size_t i = (size_t)blockIdx.x * 256 + threadIdx.x;
    float4 v = x[i];
    v.x = f2tf(v.x); v.y = f2tf(v.y); v.z = f2tf(v.z); v.w = f2tf(v.w);
    reinterpret_cast<float4*>(g_x32)[i] = v;
}

// ---------------------------------------------------------------- scores+softmax
__global__ __launch_bounds__(256) void scores_kernel() {
    const int bn = blockIdx.x;
    const int b = bn >> 3, n = bn & 7;
    const float* qb = g_qk + (size_t)b * 128 * NHW + (size_t)n * 32768;
    const float* kb = qb + 64 * NHW;

    __shared__ float Qs[64][65];
    __shared__ float Ks[64][65];

    const int t = threadIdx.x;
    const int te = (t & 15) * 4;
    const int td = (t >> 4) * 4;

    float acc[4][4] = {};

    for (int lc = 0; lc < 8; lc++) {
#pragma unroll
        for (int i = 0; i < 16; i++) {
            int id = t + i * 256;
            Qs[id >> 6][id & 63] = qb[lc * 4096 + id];
            Ks[id >> 6][id & 63] = kb[lc * 4096 + id];
        }
        __syncthreads();
#pragma unroll 8
        for (int li = 0; li < 64; li++) {
            float a[4], bb[4];
#pragma unroll
            for (int i = 0; i < 4; i++) a[i] = Qs[li][td + i];
#pragma unroll
            for (int j = 0; j < 4; j++) bb[j] = Ks[li][te + j];
#pragma unroll
            for (int i = 0; i < 4; i++)
#pragma unroll
                for (int j = 0; j < 4; j++)
                    acc[i][j] = fmaf(a[i], bb[j], acc[i][j]);
        }
        __syncthreads();
    }

#pragma unroll
    for (int i = 0; i < 4; i++)
#pragma unroll
        for (int j = 0; j < 4; j++)
            Qs[td + i][te + j] = acc[i][j] * 0.125f;
    __syncthreads();

    if (t < 64) {
        float m = -1e30f;
        for (int e = 0; e < 64; e++) m = fmaxf(m, Qs[t][e]);
        float sum = 0.f;
        for (int e = 0; e < 64; e++) { float v2 = __expf(Qs[t][e] - m); Qs[t][e] = v2; sum += v2; }
        float inv = 1.f / sum;
        for (int e = 0; e < 64; e++) Qs[t][e] *= inv;
    }
    __syncthreads();

    float* ab = g_attn + (size_t)bn * 4096;
#pragma unroll
    for (int i = 0; i < 16; i++) {
        int id = t + i * 256;
        ab[id] = Qs[id >> 6][id & 63];
    }
}

// ---------------------------------------------------------------- attn @ v
// g_mid[b, ch=d2*8+n, h, w] = sum_e attn[b,n,w,e]*v[b, c=n*64+d2, h*64+e]
// output tf32-rounded for the final GEMM.
__global__ __launch_bounds__(256) void attnv_kernel() {
    const int c = blockIdx.x;
    const int b = blockIdx.y;
    const int n = c >> 6, d2 = c & 63;
    const float* vb = g_v + ((size_t)b * NC + c) * NHW;
    const float* ab = g_attn + ((size_t)b * 8 + n) * 4096;

    __shared__ float Vs[64][65];
    __shared__ float As2[64][65];

    const int t = threadIdx.x;
    const int tw = (t & 15) * 4;
    const int th = (t >> 4) * 4;

#pragma unroll
    for (int i = 0; i < 16; i++) {
        int id = t + i * 256;
        Vs[id >> 6][id & 63] = vb[id];
        As2[id >> 6][id & 63] = ab[id];
    }
    __syncthreads();

    float acc[4][4] = {};
#pragma unroll 8
    for (int e = 0; e < 64; e++) {
        float a[4], bb[4];
#pragma unroll
        for (int i = 0; i < 4; i++) a[i] = Vs[th + i][e];
#pragma unroll
        for (int j = 0; j < 4; j++) bb[j] = As2[tw + j][e];
#pragma unroll
        for (int i = 0; i < 4; i++)
#pragma unroll
            for (int j = 0; j < 4; j++)
                acc[i][j] = fmaf(a[i], bb[j], acc[i][j]);
    }

    const int ch = d2 * 8 + n;
    float* ob = g_mid + ((size_t)b * NC + ch) * NHW;
#pragma unroll
    for (int i = 0; i < 4; i++) {
        float4 r = make_float4(f2tf(acc[i][0]), f2tf(acc[i][1]),
                               f2tf(acc[i][2]), f2tf(acc[i][3]));
        *reinterpret_cast<float4*>(&ob[(th + i) * 64 + tw]) = r;
    }
}

// ---------------------------------------------------------------- launch
extern "C" void kernel_launch(void* const* d_in, const int* in_sizes, int n_in,
                              void* d_out, int out_size) {
    (void)in_sizes; (void)n_in; (void)out_size;
    const float* x  = (const float*)d_in[0];
    const float* Wq = (const float*)d_in[1];
    const float* bq = (const float*)d_in[2];
    const float* Wk = (const float*)d_in[3];
    const float* bk = (const float*)d_in[4];
    const float* Wv = (const float*)d_in[5];
    const float* bv = (const float*)d_in[6];
    const float* Wo = (const float*)d_in[7];
    const float* bo = (const float*)d_in[8];
    float* out = (float*)d_out;

    cudaFuncSetAttribute(gemm_tf32<false>, cudaFuncAttributeMaxDynamicSharedMemorySize, SMEM_BYTES);
    cudaFuncSetAttribute(gemm_tf32<true>,  cudaFuncAttributeMaxDynamicSharedMemorySize, SMEM_BYTES);

    float *x32, *qk_p, *v_p, *mid_p, *Wqk_p, *Wv_p, *Wo_p, *bqk_p;
    cudaGetSymbolAddress((void**)&x32,  g_x32);
    cudaGetSymbolAddress((void**)&qk_p, g_qk);
    cudaGetSymbolAddress((void**)&v_p,  g_v);
    cudaGetSymbolAddress((void**)&mid_p, g_mid);
    cudaGetSymbolAddress((void**)&Wqk_p, g_Wqk);
    cudaGetSymbolAddress((void**)&Wv_p, g_Wv32);
    cudaGetSymbolAddress((void**)&Wo_p, g_Wo32);
    cudaGetSymbolAddress((void**)&bqk_p, g_bqk);

    round_w<<<dim3(1024, 3), 256>>>(Wq, bq, Wk, bk, Wv, Wo);
    round_x<<<(NB * NC * NHW) / 4 / 256, 256>>>((const float4*)x);

    // q/k projection: C[128 x 4096] per b (bias over m)
    gemm_tf32<false><<<dim3(32, 1, NB), 256, SMEM_BYTES>>>(
        Wqk_p, 0, NC, x32, (size_t)NC * NHW, NHW, bqk_p,
        qk_p, (size_t)128 * NHW, NHW);
    // v projection: C[512 x 4096] per b (bias over m)
    gemm_tf32<false><<<dim3(32, 4, NB), 256, SMEM_BYTES>>>(
        Wv_p, 0, NC, x32, (size_t)NC * NHW, NHW, bv,
        v_p, (size_t)NC * NHW, NHW);

    scores_kernel<<<128, 256>>>();
    attnv_kernel<<<dim3(512, NB), 256>>>();

    // final linear: C[4096 x 512] per b, B = Wo[n][k] k-contig, bias over n
    gemm_tf32<true><<<dim3(4, 32, NB), 256, SMEM_BYTES>>>(
        mid_p, (size_t)NC * NHW, NC, Wo_p, 0, NC, bo,
        out, (size_t)NC * NHW, NC);
}

// round 5
// speedup vs baseline: 3.1024x; 1.0307x over previous
#include <cuda_runtime.h>
#include <cstdint>

#define NB 16
#define NC 512
#define NHW 4096
#define KDIM 512

// k-permutation within each aligned 8-float block: j -> (j&3)*2 + (j>>2)
#define KPERM(o) (((o) & ~7u) | ((((o) & 3u) << 1) | (((o) >> 2) & 1u)))

// ---------------------------------------------------------------- scratch
__device__ float g_xT[(size_t)NB * NHW * NC];    // tf32-rounded, k-permuted, [b][hw][c']
__device__ float g_qk[(size_t)NB * 128 * NHW];
__device__ float g_v[(size_t)NB * NC * NHW];
__device__ float g_attn[(size_t)NB * 8 * 64 * 64];
__device__ float g_mid[(size_t)NB * NC * NHW];   // tf32-rounded, k-permuted flat view
__device__ float g_Wqk[128 * NC];                // rounded+permuted, q rows 0-63, k 64-127
__device__ float g_Wv32[NC * NC];
__device__ float g_Wo32[NC * NC];
__device__ float g_bqk[128];

__device__ __forceinline__ float f2tf(float f) {
    uint32_t o; asm("cvt.rna.tf32.f32 %0, %1;" : "=r"(o) : "f"(f));
    return __uint_as_float(o);
}

#define CP16(dst, src) asm volatile("cp.async.cg.shared.global [%0], [%1], 16;" :: "r"(dst), "l"(src) : "memory")
#define CP_COMMIT()    asm volatile("cp.async.commit_group;" ::: "memory")
#define CP_WAIT1()     asm volatile("cp.async.wait_group 1;" ::: "memory")
#define CP_WAIT0()     asm volatile("cp.async.wait_group 0;" ::: "memory")

__device__ __forceinline__ uint32_t smem_u32(const void* p) {
    uint32_t a;
    asm("{ .reg .u64 t; cvta.to.shared.u64 t, %1; cvt.u32.u64 %0, t; }" : "=r"(a) : "l"(p));
    return a;
}

// ---------------------------------------------------------------------------
// tf32 mma.sync GEMM. All operands [row][k], k-contig, tf32-prerounded and
// k-permuted within 8-blocks so fragment pairs (k, k+4) sit adjacent -> LDS.64.
// 128x128 tile, BK=32, double-buffered cp.async, 8 warps (warp tile 32x64).
// Smem row stride 40 words: LDS.64 banks (8q+2s) conflict-free.
// C[m][n] = sum_k A[m][k]*B[n][k] + bias (over m if !BIASN else over n).
// ---------------------------------------------------------------------------
#define RS 40
#define TBUF (128 * RS)                 // 5120 floats per tile buffer
#define SMEM_BYTES (4 * TBUF * 4)       // 2 bufs x (A,B) = 81920 B

template <bool BIASN>
__global__ __launch_bounds__(256, 2) void gemm_tf32(
    const float* __restrict__ A, size_t sAb,
    const float* __restrict__ B, size_t sBb,
    const float* __restrict__ bias,
    float* __restrict__ C, size_t sCb, int ldc)
{
    extern __shared__ __align__(16) float sm[];
    float* As = sm;                 // [2][128][RS]
    float* Bs = sm + 2 * TBUF;      // [2][128][RS]
    const uint32_t sA = smem_u32(As), sB = smem_u32(Bs);

    const int b  = blockIdx.z;
    const int n0 = blockIdx.x * 128;
    const int m0 = blockIdx.y * 128;
    const float* Ap = A + (size_t)b * sAb + (size_t)m0 * KDIM;
    const float* Bp = B + (size_t)b * sBb + (size_t)n0 * KDIM;

    const int t = threadIdx.x, lane = t & 31, w = t >> 5;
    const int wm = (w & 3) * 32;
    const int wn = (w >> 2) * 64;
    const int q = lane >> 2, s = lane & 3;

    float acc[2][8][4] = {};

    auto ld_tiles = [&](int buf, int ko) {
#pragma unroll
        for (int i = 0; i < 4; i++) {
            int id = t + i * 256;
            int r = id >> 3, c4 = (id & 7) * 4;
            CP16(sA + (uint32_t)(buf * TBUF + r * RS + c4) * 4,
                 Ap + (size_t)r * KDIM + ko + c4);
            CP16(sB + (uint32_t)(buf * TBUF + r * RS + c4) * 4,
                 Bp + (size_t)r * KDIM + ko + c4);
        }
        CP_COMMIT();
    };

    ld_tiles(0, 0);

    const int NIT = KDIM / 32;
    for (int it = 0; it < NIT; it++) {
        const int buf = it & 1;
        if (it < NIT - 1) { ld_tiles(buf ^ 1, (it + 1) * 32); CP_WAIT1(); }
        else              { CP_WAIT0(); }
        __syncthreads();

        const float* Ab = As + buf * TBUF;
        const float* Bb = Bs + buf * TBUF;
#pragma unroll
        for (int kk = 0; kk < 4; kk++) {
            const int kc = kk * 8 + s * 2;
            uint32_t af[2][4];
#pragma unroll
            for (int mi = 0; mi < 2; mi++) {
                const int rb = wm + mi * 16 + q;
                float2 a02 = *reinterpret_cast<const float2*>(&Ab[rb * RS + kc]);
                float2 a13 = *reinterpret_cast<const float2*>(&Ab[(rb + 8) * RS + kc]);
                af[mi][0] = __float_as_uint(a02.x);
                af[mi][1] = __float_as_uint(a13.x);
                af[mi][2] = __float_as_uint(a02.y);
                af[mi][3] = __float_as_uint(a13.y);
            }
#pragma unroll
            for (int ni = 0; ni < 8; ni++) {
                const int nb = wn + ni * 8 + q;
                float2 bp = *reinterpret_cast<const float2*>(&Bb[nb * RS + kc]);
                uint32_t b0 = __float_as_uint(bp.x), b1 = __float_as_uint(bp.y);
#pragma unroll
                for (int mi = 0; mi < 2; mi++) {
                    asm volatile(
                        "mma.sync.aligned.m16n8k8.row.col.f32.tf32.tf32.f32 "
                        "{%0,%1,%2,%3},{%4,%5,%6,%7},{%8,%9},{%0,%1,%2,%3};"
                        : "+f"(acc[mi][ni][0]), "+f"(acc[mi][ni][1]),
                          "+f"(acc[mi][ni][2]), "+f"(acc[mi][ni][3])
                        : "r"(af[mi][0]), "r"(af[mi][1]), "r"(af[mi][2]), "r"(af[mi][3]),
                          "r"(b0), "r"(b1));
                }
            }
        }
        __syncthreads();
    }

    float* Cp = C + (size_t)b * sCb;
#pragma unroll
    for (int mi = 0; mi < 2; mi++) {
        int r0 = m0 + wm + mi * 16 + q;
#pragma unroll
        for (int ni = 0; ni < 8; ni++) {
            int c0 = n0 + wn + ni * 8 + s * 2;
#pragma unroll
            for (int rr = 0; rr < 2; rr++) {
                int r = r0 + rr * 8;
                float v0 = acc[mi][ni][rr * 2], v1 = acc[mi][ni][rr * 2 + 1];
                if (BIASN) { v0 += bias[c0]; v1 += bias[c0 + 1]; }
                else       { float bv = bias[r]; v0 += bv; v1 += bv; }
                *reinterpret_cast<float2*>(&Cp[(size_t)r * ldc + c0]) = make_float2(v0, v1);
            }
        }
    }
}

// ---------------------------------------------------------------- pre-passes
// Round weights to tf32 and permute k within 8-blocks.
__global__ void round_w(const float* __restrict__ Wq, const float* __restrict__ bq,
                        const float* __restrict__ Wk, const float* __restrict__ bk,
                        const float* __restrict__ Wv, const float* __restrict__ Wo) {
    uint32_t idx = blockIdx.x * 256 + threadIdx.x;
    int job = blockIdx.y;
    uint32_t pidx = (idx & ~511u) | KPERM(idx & 511u);
    if (job == 0) {
        if (idx < NC * NC) g_Wv32[pidx] = f2tf(Wv[idx]);
    } else if (job == 1) {
        if (idx < NC * NC) g_Wo32[pidx] = f2tf(Wo[idx]);
    } else {
        if (idx < 64 * NC) {
            g_Wqk[pidx] = f2tf(Wq[idx]);
            g_Wqk[64 * NC + pidx] = f2tf(Wk[idx]);
        }
        if (idx < 64) { g_bqk[idx] = bq[idx]; g_bqk[64 + idx] = bk[idx]; }
    }
}

// x[b][c][hw] -> xT[b][hw][perm(c)] tf32-rounded.
__global__ __launch_bounds__(256) void transpose_x(const float* __restrict__ x) {
    __shared__ float ts[32][33];
    const int b = blockIdx.z;
    const int hw0 = blockIdx.x * 32, c0 = blockIdx.y * 32;
    const int tx = threadIdx.x, ty = threadIdx.y;
    const float* xb = x + (size_t)b * NC * NHW;
#pragma unroll
    for (int i = 0; i < 4; i++) {
        int r = ty + i * 8;
        ts[r][tx] = xb[(size_t)(c0 + r) * NHW + hw0 + tx];
    }
    __syncthreads();
    const uint32_t c = c0 + tx;
    const uint32_t cp = (c & ~7u) | KPERM(c & 7u);
#pragma unroll
    for (int i = 0; i < 4; i++) {
        int r = ty + i * 8;
        g_xT[(size_t)b * NHW * NC + (size_t)(hw0 + r) * NC + cp] = f2tf(ts[tx][r]);
    }
}

// ---------------------------------------------------------------- scores+softmax
__global__ __launch_bounds__(256) void scores_kernel() {
    const int bn = blockIdx.x;
    const int b = bn >> 3, n = bn & 7;
    const float* qb = g_qk + (size_t)b * 128 * NHW + (size_t)n * 32768;
    const float* kb = qb + 64 * NHW;

    __shared__ float Qs[64][65];
    __shared__ float Ks[64][65];

    const int t = threadIdx.x;
    const int te = (t & 15) * 4;
    const int td = (t >> 4) * 4;

    float acc[4][4] = {};

    for (int lc = 0; lc < 8; lc++) {
#pragma unroll
        for (int i = 0; i < 16; i++) {
            int id = t + i * 256;
            Qs[id >> 6][id & 63] = qb[lc * 4096 + id];
            Ks[id >> 6][id & 63] = kb[lc * 4096 + id];
        }
        __syncthreads();
#pragma unroll 8
        for (int li = 0; li < 64; li++) {
            float a[4], bb[4];
#pragma unroll
            for (int i = 0; i < 4; i++) a[i] = Qs[li][td + i];
#pragma unroll
            for (int j = 0; j < 4; j++) bb[j] = Ks[li][te + j];
#pragma unroll
            for (int i = 0; i < 4; i++)
#pragma unroll
                for (int j = 0; j < 4; j++)
                    acc[i][j] = fmaf(a[i], bb[j], acc[i][j]);
        }
        __syncthreads();
    }

#pragma unroll
    for (int i = 0; i < 4; i++)
#pragma unroll
        for (int j = 0; j < 4; j++)
            Qs[td + i][te + j] = acc[i][j] * 0.125f;
    __syncthreads();

    if (t < 64) {
        float m = -1e30f;
        for (int e = 0; e < 64; e++) m = fmaxf(m, Qs[t][e]);
        float sum = 0.f;
        for (int e = 0; e < 64; e++) { float v2 = __expf(Qs[t][e] - m); Qs[t][e] = v2; sum += v2; }
        float inv = 1.f / sum;
        for (int e = 0; e < 64; e++) Qs[t][e] *= inv;
    }
    __syncthreads();

    float* ab = g_attn + (size_t)bn * 4096;
#pragma unroll
    for (int i = 0; i < 16; i++) {
        int id = t + i * 256;
        ab[id] = Qs[id >> 6][id & 63];
    }
}

// ---------------------------------------------------------------- attn @ v
// mid value at flat offset o = ch*4096 + h*64 + w stored at k-permuted slot
// (perm over o&7) so the final GEMM's A fragments are LDS.64-ready.
__global__ __launch_bounds__(256) void attnv_kernel() {
    const int c = blockIdx.x;
    const int b = blockIdx.y;
    const int n = c >> 6, d2 = c & 63;
    const float* vb = g_v + ((size_t)b * NC + c) * NHW;
    const float* ab = g_attn + ((size_t)b * 8 + n) * 4096;

    __shared__ float Vs[64][65];
    __shared__ float As2[64][65];

    const int t = threadIdx.x;
    const int tw = (t & 15) * 4;
    const int th = (t >> 4) * 4;

#pragma unroll
    for (int i = 0; i < 16; i++) {
        int id = t + i * 256;
        Vs[id >> 6][id & 63] = vb[id];
        As2[id >> 6][id & 63] = ab[id];
    }
    __syncthreads();

    float acc[4][4] = {};
#pragma unroll 8
    for (int e = 0; e < 64; e++) {
        float a[4], bb[4];
#pragma unroll
        for (int i = 0; i < 4; i++) a[i] = Vs[th + i][e];
#pragma unroll
        for (int j = 0; j < 4; j++) bb[j] = As2[tw + j][e];
#pragma unroll
        for (int i = 0; i < 4; i++)
#pragma unroll
            for (int j = 0; j < 4; j++)
                acc[i][j] = fmaf(a[i], bb[j], acc[i][j]);
    }

    const int ch = d2 * 8 + n;
    float* mb = g_mid + (size_t)b * NC * NHW;
#pragma unroll
    for (int i = 0; i < 4; i++) {
        uint32_t o_base = ch * 4096 + (th + i) * 64 + tw;
#pragma unroll
        for (int j = 0; j < 4; j++) {
            uint32_t o = o_base + j;
            mb[(o & ~7u) | KPERM(o & 7u)] = f2tf(acc[i][j]);
        }
    }
}

// ---------------------------------------------------------------- launch
extern "C" void kernel_launch(void* const* d_in, const int* in_sizes, int n_in,
                              void* d_out, int out_size) {
    (void)in_sizes; (void)n_in; (void)out_size;
    const float* x  = (const float*)d_in[0];
    const float* Wq = (const float*)d_in[1];
    const float* bq = (const float*)d_in[2];
    const float* Wk = (const float*)d_in[3];
    const float* bk = (const float*)d_in[4];
    const float* Wv = (const float*)d_in[5];
    const float* bv = (const float*)d_in[6];
    const float* Wo = (const float*)d_in[7];
    const float* bo = (const float*)d_in[8];
    float* out = (float*)d_out;

    cudaFuncSetAttribute(gemm_tf32<false>, cudaFuncAttributeMaxDynamicSharedMemorySize, SMEM_BYTES);
    cudaFuncSetAttribute(gemm_tf32<true>,  cudaFuncAttributeMaxDynamicSharedMemorySize, SMEM_BYTES);

    float *xT, *qk_p, *v_p, *mid_p, *Wqk_p, *Wv_p, *Wo_p, *bqk_p;
    cudaGetSymbolAddress((void**)&xT,    g_xT);
    cudaGetSymbolAddress((void**)&qk_p,  g_qk);
    cudaGetSymbolAddress((void**)&v_p,   g_v);
    cudaGetSymbolAddress((void**)&mid_p, g_mid);
    cudaGetSymbolAddress((void**)&Wqk_p, g_Wqk);
    cudaGetSymbolAddress((void**)&Wv_p,  g_Wv32);
    cudaGetSymbolAddress((void**)&Wo_p,  g_Wo32);
    cudaGetSymbolAddress((void**)&bqk_p, g_bqk);

    round_w<<<dim3(1024, 3), 256>>>(Wq, bq, Wk, bk, Wv, Wo);
    transpose_x<<<dim3(128, 16, 16), dim3(32, 8)>>>(x);

    // q/k projection: C[128 x 4096] per b (bias over m)
    gemm_tf32<false><<<dim3(32, 1, NB), 256, SMEM_BYTES>>>(
        Wqk_p, 0, xT, (size_t)NHW * NC, bqk_p,
        qk_p, (size_t)128 * NHW, NHW);
    // v projection: C[512 x 4096] per b (bias over m)
    gemm_tf32<false><<<dim3(32, 4, NB), 256, SMEM_BYTES>>>(
        Wv_p, 0, xT, (size_t)NHW * NC, bv,
        v_p, (size_t)NC * NHW, NHW);

    scores_kernel<<<128, 256>>>();
    attnv_kernel<<<dim3(512, NB), 256>>>();

    // final linear: C[4096 x 512] per b (bias over n)
    gemm_tf32<true><<<dim3(4, 32, NB), 256, SMEM_BYTES>>>(
        mid_p, (size_t)NC * NHW, Wo_p, 0, bo,
        out, (size_t)NC * NHW, NC);
}

// round 6
// speedup vs baseline: 3.1971x; 1.0305x over previous
#include <cuda_runtime.h>
#include <cstdint>

#define NB 16
#define NC 512
#define NHW 4096
#define KDIM 512

// ---------------------------------------------------------------- scratch
// Fragment-major layouts (see idxA/idxB):
__device__ float g_xT[(size_t)NB * NHW * NC];    // B-layout (n=hw, k=c), tf32
__device__ float g_qk[(size_t)NB * 128 * NHW];   // row-major
__device__ float g_v[(size_t)NB * NC * NHW];     // row-major
__device__ float g_attn[(size_t)NB * 8 * 64 * 64];
__device__ float g_mid[(size_t)NB * NC * NHW];   // A-layout (r=flat4096, k=c), tf32
__device__ float g_Wqk[128 * NC];                // A-layout, q rows 0-63, k rows 64-127
__device__ float g_Wv32[NC * NC];                // A-layout
__device__ float g_Wo32[NC * NC];                // B-layout (n=o, k=c)
__device__ float g_bqk[128];

__device__ __forceinline__ float f2tf(float f) {
    uint32_t o; asm("cvt.rna.tf32.f32 %0, %1;" : "=r"(o) : "f"(f));
    return __uint_as_float(o);
}

// A-fragment-major: 16m x 8k blocks, ordered [M128][kb8][mb16][lane][slot]
__device__ __forceinline__ uint32_t idxA(uint32_t m, uint32_t k) {
    return ((((m >> 7) * (KDIM / 8) + (k >> 3)) * 8 + ((m & 127) >> 4)) * 32
            + (((m & 7) << 2) | (k & 3))) * 4
           + (((m >> 3) & 1) | (((k >> 2) & 1) << 1));
}
// B-fragment-major: 8n x 16k blocks, ordered [N128][kb16][nb8][lane][slot]
__device__ __forceinline__ uint32_t idxB(uint32_t n, uint32_t k) {
    return ((((n >> 7) * (KDIM / 16) + (k >> 4)) * 16 + ((n & 127) >> 3)) * 32
            + (((n & 7) << 2) | (k & 3))) * 4
           + ((k >> 2) & 3);
}

#define CP16(dst, src) asm volatile("cp.async.cg.shared.global [%0], [%1], 16;" :: "r"(dst), "l"(src) : "memory")
#define CP_COMMIT()    asm volatile("cp.async.commit_group;" ::: "memory")
#define CP_WAIT1()     asm volatile("cp.async.wait_group 1;" ::: "memory")
#define CP_WAIT0()     asm volatile("cp.async.wait_group 0;" ::: "memory")

__device__ __forceinline__ uint32_t smem_u32(const void* p) {
    uint32_t a;
    asm("{ .reg .u64 t; cvta.to.shared.u64 t, %1; cvt.u32.u64 %0, t; }" : "=r"(a) : "l"(p));
    return a;
}

// ---------------------------------------------------------------------------
// tf32 mma.sync GEMM over fragment-major operands.
// CTA tile 128x128, BK=32, double-buffered cp.async, 8 warps (32m x 64n each).
// All fragment loads are conflict-free LDS.128 with immediate offsets.
// C[m][n] = sum_k A[m][k]*B[n][k] + bias (over m if !BIASN else over n).
// ---------------------------------------------------------------------------
#define SMEM_BYTES 65536    // 2 bufs x (A 16KB + B 16KB)

template <bool BIASN>
__global__ __launch_bounds__(256, 2) void gemm_tf32(
    const float* __restrict__ A, size_t sAb,
    const float* __restrict__ B, size_t sBb,
    const float* __restrict__ bias,
    float* __restrict__ C, size_t sCb, int ldc)
{
    extern __shared__ __align__(16) float sm[];
    const uint32_t smb = smem_u32(sm);
    const int b  = blockIdx.z;
    const int n0 = blockIdx.x * 128;
    const int m0 = blockIdx.y * 128;
    const float* Ag = A + (size_t)b * sAb + (size_t)(m0 >> 7) * 65536;
    const float* Bg = B + (size_t)b * sBb + (size_t)(n0 >> 7) * 65536;

    const int t = threadIdx.x, lane = t & 31, w = t >> 5;
    const int wm16 = (w & 3) * 2;    // warp's first 16-row block (2 blocks)
    const int wn8  = (w >> 2) * 8;   // warp's first 8-col block (8 blocks)
    const int q = lane >> 2, s = lane & 3;

    float acc[2][8][4] = {};

    auto fill = [&](int buf, int ko) {
        const float* sa = Ag + (ko >> 3) * 1024;    // 4 kb8 blocks = 4096 floats
        const float* sb = Bg + (ko >> 4) * 2048;    // 2 kb16 blocks = 4096 floats
        uint32_t da = smb + buf * 32768 + t * 16;
#pragma unroll
        for (int i = 0; i < 4; i++) CP16(da + i * 4096, sa + t * 4 + i * 1024);
#pragma unroll
        for (int i = 0; i < 4; i++) CP16(da + 16384 + i * 4096, sb + t * 4 + i * 1024);
        CP_COMMIT();
    };

    fill(0, 0);

    for (int it = 0; it < KDIM / 32; it++) {
        const int buf = it & 1;
        if (it < KDIM / 32 - 1) { fill(buf ^ 1, (it + 1) * 32); CP_WAIT1(); }
        else                    { CP_WAIT0(); }
        __syncthreads();

        const float4* At = reinterpret_cast<const float4*>(sm) + buf * 2048;
        const float4* Bt = At + 1024;
#pragma unroll
        for (int kp = 0; kp < 2; kp++) {
            float4 af[2][2];
#pragma unroll
            for (int kkl = 0; kkl < 2; kkl++)
#pragma unroll
                for (int mi = 0; mi < 2; mi++)
                    af[mi][kkl] = At[((kp * 2 + kkl) * 8 + wm16 + mi) * 32 + lane];
#pragma unroll
            for (int nh = 0; nh < 2; nh++) {
                float4 bf[4];
#pragma unroll
                for (int nj = 0; nj < 4; nj++)
                    bf[nj] = Bt[(kp * 16 + wn8 + nh * 4 + nj) * 32 + lane];
#pragma unroll
                for (int kkl = 0; kkl < 2; kkl++)
#pragma unroll
                    for (int nj = 0; nj < 4; nj++) {
                        const int ni = nh * 4 + nj;
                        uint32_t b0 = __float_as_uint(kkl ? bf[nj].z : bf[nj].x);
                        uint32_t b1 = __float_as_uint(kkl ? bf[nj].w : bf[nj].y);
#pragma unroll
                        for (int mi = 0; mi < 2; mi++) {
                            asm volatile(
                                "mma.sync.aligned.m16n8k8.row.col.f32.tf32.tf32.f32 "
                                "{%0,%1,%2,%3},{%4,%5,%6,%7},{%8,%9},{%0,%1,%2,%3};"
                                : "+f"(acc[mi][ni][0]), "+f"(acc[mi][ni][1]),
                                  "+f"(acc[mi][ni][2]), "+f"(acc[mi][ni][3])
                                : "r"(__float_as_uint(af[mi][kkl].x)),
                                  "r"(__float_as_uint(af[mi][kkl].y)),
                                  "r"(__float_as_uint(af[mi][kkl].z)),
                                  "r"(__float_as_uint(af[mi][kkl].w)),
                                  "r"(b0), "r"(b1));
                        }
                    }
            }
        }
        __syncthreads();
    }

    float* Cp = C + (size_t)b * sCb;
#pragma unroll
    for (int mi = 0; mi < 2; mi++) {
        int r0 = m0 + (wm16 + mi) * 16 + q;
#pragma unroll
        for (int ni = 0; ni < 8; ni++) {
            int c0 = n0 + (wn8 + ni) * 8 + s * 2;
#pragma unroll
            for (int rr = 0; rr < 2; rr++) {
                int r = r0 + rr * 8;
                float v0 = acc[mi][ni][rr * 2], v1 = acc[mi][ni][rr * 2 + 1];
                if (BIASN) { v0 += bias[c0]; v1 += bias[c0 + 1]; }
                else       { float bv = bias[r]; v0 += bv; v1 += bv; }
                *reinterpret_cast<float2*>(&Cp[(size_t)r * ldc + c0]) = make_float2(v0, v1);
            }
        }
    }
}

// ---------------------------------------------------------------- pre-passes
__global__ void round_w(const float* __restrict__ Wq, const float* __restrict__ bq,
                        const float* __restrict__ Wk, const float* __restrict__ bk,
                        const float* __restrict__ Wv, const float* __restrict__ Wo) {
    uint32_t idx = blockIdx.x * 256 + threadIdx.x;
    int job = blockIdx.y;
    if (job == 0) {
        if (idx < NC * NC) g_Wv32[idxA(idx >> 9, idx & 511)] = f2tf(Wv[idx]);
    } else if (job == 1) {
        if (idx < NC * NC) g_Wo32[idxB(idx >> 9, idx & 511)] = f2tf(Wo[idx]);
    } else {
        if (idx < 64 * NC) {
            uint32_t m = idx >> 9, c = idx & 511;
            g_Wqk[idxA(m, c)]      = f2tf(Wq[idx]);
            g_Wqk[idxA(m + 64, c)] = f2tf(Wk[idx]);
        }
        if (idx < 64) { g_bqk[idx] = bq[idx]; g_bqk[64 + idx] = bk[idx]; }
    }
}

// x[b][c][hw] -> xT B-fragment layout (n=hw, k=c), tf32-rounded.
__global__ __launch_bounds__(256) void transpose_x(const float* __restrict__ x) {
    __shared__ float ts[32][33];
    const int b = blockIdx.z;
    const int hw0 = blockIdx.x * 32, c0 = blockIdx.y * 32;
    const int tx = threadIdx.x, ty = threadIdx.y;
    const float* xb = x + (size_t)b * NC * NHW;
#pragma unroll
    for (int i = 0; i < 4; i++) {
        int r = ty + i * 8;
        ts[r][tx] = xb[(size_t)(c0 + r) * NHW + hw0 + tx];
    }
    __syncthreads();
    float* ob = g_xT + (size_t)b * NHW * NC;
#pragma unroll
    for (int i = 0; i < 4; i++) {
        int r = ty + i * 8;
        ob[idxB(hw0 + r, c0 + tx)] = f2tf(ts[tx][r]);
    }
}

// ---------------------------------------------------------------- scores+softmax
__global__ __launch_bounds__(256) void scores_kernel() {
    const int bn = blockIdx.x;
    const int b = bn >> 3, n = bn & 7;
    const float* qb = g_qk + (size_t)b * 128 * NHW + (size_t)n * 32768;
    const float* kb = qb + 64 * NHW;

    __shared__ float Qs[64][65];
    __shared__ float Ks[64][65];

    const int t = threadIdx.x;
    const int te = (t & 15) * 4;
    const int td = (t >> 4) * 4;

    float acc[4][4] = {};

    for (int lc = 0; lc < 8; lc++) {
#pragma unroll
        for (int i = 0; i < 16; i++) {
            int id = t + i * 256;
            Qs[id >> 6][id & 63] = qb[lc * 4096 + id];
            Ks[id >> 6][id & 63] = kb[lc * 4096 + id];
        }
        __syncthreads();
#pragma unroll 8
        for (int li = 0; li < 64; li++) {
            float a[4], bb[4];
#pragma unroll
            for (int i = 0; i < 4; i++) a[i] = Qs[li][td + i];
#pragma unroll
            for (int j = 0; j < 4; j++) bb[j] = Ks[li][te + j];
#pragma unroll
            for (int i = 0; i < 4; i++)
#pragma unroll
                for (int j = 0; j < 4; j++)
                    acc[i][j] = fmaf(a[i], bb[j], acc[i][j]);
        }
        __syncthreads();
    }

#pragma unroll
    for (int i = 0; i < 4; i++)
#pragma unroll
        for (int j = 0; j < 4; j++)
            Qs[td + i][te + j] = acc[i][j] * 0.125f;
    __syncthreads();

    if (t < 64) {
        float m = -1e30f;
        for (int e = 0; e < 64; e++) m = fmaxf(m, Qs[t][e]);
        float sum = 0.f;
        for (int e = 0; e < 64; e++) { float v2 = __expf(Qs[t][e] - m); Qs[t][e] = v2; sum += v2; }
        float inv = 1.f / sum;
        for (int e = 0; e < 64; e++) Qs[t][e] *= inv;
    }
    __syncthreads();

    float* ab = g_attn + (size_t)bn * 4096;
#pragma unroll
    for (int i = 0; i < 16; i++) {
        int id = t + i * 256;
        ab[id] = Qs[id >> 6][id & 63];
    }
}

// ---------------------------------------------------------------- attn @ v
// mid flat offset o = ch*4096 + h*64 + w  ->  GEMM-A row r = o>>9, k = o&511,
// stored in A-fragment layout for the final GEMM.
__global__ __launch_bounds__(256) void attnv_kernel() {
    const int c = blockIdx.x;
    const int b = blockIdx.y;
    const int n = c >> 6, d2 = c & 63;
    const float* vb = g_v + ((size_t)b * NC + c) * NHW;
    const float* ab = g_attn + ((size_t)b * 8 + n) * 4096;

    __shared__ float Vs[64][65];
    __shared__ float As2[64][65];

    const int t = threadIdx.x;
    const int tw = (t & 15) * 4;
    const int th = (t >> 4) * 4;

#pragma unroll
    for (int i = 0; i < 16; i++) {
        int id = t + i * 256;
        Vs[id >> 6][id & 63] = vb[id];
        As2[id >> 6][id & 63] = ab[id];
    }
    __syncthreads();

    float acc[4][4] = {};
#pragma unroll 8
    for (int e = 0; e < 64; e++) {
        float a[4], bb[4];
#pragma unroll
        for (int i = 0; i < 4; i++) a[i] = Vs[th + i][e];
#pragma unroll
        for (int j = 0; j < 4; j++) bb[j] = As2[tw + j][e];
#pragma unroll
        for (int i = 0; i < 4; i++)
#pragma unroll
            for (int j = 0; j < 4; j++)
                acc[i][j] = fmaf(a[i], bb[j], acc[i][j]);
    }

    const int ch = d2 * 8 + n;
    float* mb = g_mid + (size_t)b * NC * NHW;
#pragma unroll
    for (int i = 0; i < 4; i++) {
        uint32_t r = ch * 8 + ((th + i) >> 3);
        uint32_t kc0 = ((th + i) & 7) * 64 + tw;
#pragma unroll
        for (int j = 0; j < 4; j++)
            mb[idxA(r, kc0 + j)] = f2tf(acc[i][j]);
    }
}

// ---------------------------------------------------------------- launch
extern "C" void kernel_launch(void* const* d_in, const int* in_sizes, int n_in,
                              void* d_out, int out_size) {
    (void)in_sizes; (void)n_in; (void)out_size;
    const float* x  = (const float*)d_in[0];
    const float* Wq = (const float*)d_in[1];
    const float* bq = (const float*)d_in[2];
    const float* Wk = (const float*)d_in[3];
    const float* bk = (const float*)d_in[4];
    const float* Wv = (const float*)d_in[5];
    const float* bv = (const float*)d_in[6];
    const float* Wo = (const float*)d_in[7];
    const float* bo = (const float*)d_in[8];
    float* out = (float*)d_out;

    cudaFuncSetAttribute(gemm_tf32<false>, cudaFuncAttributeMaxDynamicSharedMemorySize, SMEM_BYTES);
    cudaFuncSetAttribute(gemm_tf32<true>,  cudaFuncAttributeMaxDynamicSharedMemorySize, SMEM_BYTES);

    float *xT, *qk_p, *v_p, *mid_p, *Wqk_p, *Wv_p, *Wo_p, *bqk_p;
    cudaGetSymbolAddress((void**)&xT,    g_xT);
    cudaGetSymbolAddress((void**)&qk_p,  g_qk);
    cudaGetSymbolAddress((void**)&v_p,   g_v);
    cudaGetSymbolAddress((void**)&mid_p, g_mid);
    cudaGetSymbolAddress((void**)&Wqk_p, g_Wqk);
    cudaGetSymbolAddress((void**)&Wv_p,  g_Wv32);
    cudaGetSymbolAddress((void**)&Wo_p,  g_Wo32);
    cudaGetSymbolAddress((void**)&bqk_p, g_bqk);

    round_w<<<dim3(1024, 3), 256>>>(Wq, bq, Wk, bk, Wv, Wo);
    transpose_x<<<dim3(128, 16, 16), dim3(32, 8)>>>(x);

    // q/k projection: C[128 x 4096] per b (bias over m)
    gemm_tf32<false><<<dim3(32, 1, NB), 256, SMEM_BYTES>>>(
        Wqk_p, 0, xT, (size_t)NHW * NC, bqk_p,
        qk_p, (size_t)128 * NHW, NHW);
    // v projection: C[512 x 4096] per b (bias over m)
    gemm_tf32<false><<<dim3(32, 4, NB), 256, SMEM_BYTES>>>(
        Wv_p, 0, xT, (size_t)NHW * NC, bv,
        v_p, (size_t)NC * NHW, NHW);

    scores_kernel<<<128, 256>>>();
    attnv_kernel<<<dim3(512, NB), 256>>>();

    // final linear: C[4096 x 512] per b (bias over n)
    gemm_tf32<true><<<dim3(4, 32, NB), 256, SMEM_BYTES>>>(
        mid_p, (size_t)NC * NHW, Wo_p, 0, bo,
        out, (size_t)NC * NHW, NC);
}

// round 12
// speedup vs baseline: 3.6989x; 1.1570x over previous
#include <cuda_runtime.h>
#include <cstdint>

#define NB 16
#define NC 512
#define NHW 4096
#define KDIM 512

// k-permutation within each aligned 8-float block: j -> (j&3)*2 + (j>>2)
#define KPERM(o) (((o) & ~7u) | ((((o) & 3u) << 1) | (((o) >> 2) & 1u)))

// ---------------------------------------------------------------- scratch
__device__ float g_xT[(size_t)NB * NHW * NC];    // B-fragment layout (n=hw,k=c)
__device__ float g_qk[(size_t)NB * 128 * NHW];   // row-major
__device__ float g_v[(size_t)NB * NC * NHW];     // row-major
__device__ float g_attn[(size_t)NB * 8 * 64 * 64];
__device__ float g_mid[(size_t)NB * NC * NHW];   // KPERM row-major, tf32
__device__ float g_Wqk[128 * NC];                // A-fragment layout
__device__ float g_Wv32[NC * NC];                // A-fragment layout
__device__ float g_Wo32[NC * NC];                // B-fragment layout
__device__ float g_bqk[128];

__device__ __forceinline__ float f2tf(float f) {
    uint32_t o; asm("cvt.rna.tf32.f32 %0, %1;" : "=r"(o) : "f"(f));
    return __uint_as_float(o);
}

// A-fragment-major: 16m x 8k blocks, ordered [M128][kb8][mb16][lane][slot]
__device__ __forceinline__ uint32_t idxA(uint32_t m, uint32_t k) {
    return ((((m >> 7) * (KDIM / 8) + (k >> 3)) * 8 + ((m & 127) >> 4)) * 32
            + (((m & 7) << 2) | (k & 3))) * 4
           + (((m >> 3) & 1) | (((k >> 2) & 1) << 1));
}
// B-fragment-major: 8n x 16k blocks, ordered [N128][kb16][nb8][lane][slot]
__device__ __forceinline__ uint32_t idxB(uint32_t n, uint32_t k) {
    return ((((n >> 7) * (KDIM / 16) + (k >> 4)) * 16 + ((n & 127) >> 3)) * 32
            + (((n & 7) << 2) | (k & 3))) * 4
           + ((k >> 2) & 3);
}

#define CP16(dst, src) asm volatile("cp.async.cg.shared.global [%0], [%1], 16;" :: "r"(dst), "l"(src) : "memory")
#define CP_COMMIT()    asm volatile("cp.async.commit_group;" ::: "memory")
#define CP_WAIT2()     asm volatile("cp.async.wait_group 2;" ::: "memory")
#define CP_WAIT1()     asm volatile("cp.async.wait_group 1;" ::: "memory")
#define CP_WAIT0()     asm volatile("cp.async.wait_group 0;" ::: "memory")

__device__ __forceinline__ uint32_t smem_u32(const void* p) {
    uint32_t a;
    asm("{ .reg .u64 t; cvta.to.shared.u64 t, %1; cvt.u32.u64 %0, t; }" : "=r"(a) : "l"(p));
    return a;
}

#define MMA_TF32(acc, a0, a1, a2, a3, b0, b1) \
    asm volatile("mma.sync.aligned.m16n8k8.row.col.f32.tf32.tf32.f32 " \
        "{%0,%1,%2,%3},{%4,%5,%6,%7},{%8,%9},{%0,%1,%2,%3};" \
        : "+f"((acc)[0]), "+f"((acc)[1]), "+f"((acc)[2]), "+f"((acc)[3]) \
        : "r"(a0), "r"(a1), "r"(a2), "r"(a3), "r"(b0), "r"(b1))

// ---------------------------------------------------------------------------
// Projection GEMM: both operands fragment-major, 3-stage cp.async pipeline.
// CTA tile 128x128, BK=32, 8 warps. C[m][n] = sum_k A[m][k]*B[n][k] + bias[m].
// ---------------------------------------------------------------------------
#define PROJ_SMEM (3 * 32768)

__global__ __launch_bounds__(256, 2) void gemm_proj(
    const float* __restrict__ A, size_t sAb,
    const float* __restrict__ B, size_t sBb,
    const float* __restrict__ bias,
    float* __restrict__ C, size_t sCb, int ldc)
{
    extern __shared__ __align__(16) float sm[];
    const uint32_t smb = smem_u32(sm);
    const int b  = blockIdx.z;
    const int n0 = blockIdx.x * 128;
    const int m0 = blockIdx.y * 128;
    const float* Ag = A + (size_t)b * sAb + (size_t)(m0 >> 7) * 65536;
    const float* Bg = B + (size_t)b * sBb + (size_t)(n0 >> 7) * 65536;

    const int t = threadIdx.x, lane = t & 31, w = t >> 5;
    const int wm16 = (w & 3) * 2;
    const int wn8  = (w >> 2) * 8;
    const int q = lane >> 2, s = lane & 3;

    float acc[2][8][4] = {};

    auto fill = [&](int buf, int it) {
        const int ko = it * 32;
        const float* sa = Ag + (ko >> 3) * 1024;
        const float* sb = Bg + (ko >> 4) * 2048;
        uint32_t da = smb + buf * 32768 + t * 16;
#pragma unroll
        for (int i = 0; i < 4; i++) CP16(da + i * 4096, sa + t * 4 + i * 1024);
#pragma unroll
        for (int i = 0; i < 4; i++) CP16(da + 16384 + i * 4096, sb + t * 4 + i * 1024);
        CP_COMMIT();
    };

    fill(0, 0); fill(1, 1);
    int fb = 2;

    for (int it = 0; it < 16; it++) {
        const int buf = it % 3;
        __syncthreads();
        if (it <= 13) { fill(fb, it + 2); fb = (fb == 2) ? 0 : fb + 1; CP_WAIT2(); }
        else if (it == 14) CP_WAIT1();
        else CP_WAIT0();
        __syncthreads();

        const float4* At = reinterpret_cast<const float4*>(sm) + buf * 2048;
        const float4* Bt = At + 1024;
#pragma unroll
        for (int kp = 0; kp < 2; kp++) {
            float4 af[2][2];
#pragma unroll
            for (int kkl = 0; kkl < 2; kkl++)
#pragma unroll
                for (int mi = 0; mi < 2; mi++)
                    af[mi][kkl] = At[((kp * 2 + kkl) * 8 + wm16 + mi) * 32 + lane];
#pragma unroll
            for (int nh = 0; nh < 2; nh++) {
                float4 bf[4];
#pragma unroll
                for (int nj = 0; nj < 4; nj++)
                    bf[nj] = Bt[(kp * 16 + wn8 + nh * 4 + nj) * 32 + lane];
#pragma unroll
                for (int kkl = 0; kkl < 2; kkl++)
#pragma unroll
                    for (int nj = 0; nj < 4; nj++) {
                        const int ni = nh * 4 + nj;
                        uint32_t b0 = __float_as_uint(kkl ? bf[nj].z : bf[nj].x);
                        uint32_t b1 = __float_as_uint(kkl ? bf[nj].w : bf[nj].y);
#pragma unroll
                        for (int mi = 0; mi < 2; mi++)
                            MMA_TF32(acc[mi][ni],
                                     __float_as_uint(af[mi][kkl].x),
                                     __float_as_uint(af[mi][kkl].y),
                                     __float_as_uint(af[mi][kkl].z),
                                     __float_as_uint(af[mi][kkl].w), b0, b1);
                    }
            }
        }
    }

    float* Cp = C + (size_t)b * sCb;
#pragma unroll
    for (int mi = 0; mi < 2; mi++) {
        int r0 = m0 + (wm16 + mi) * 16 + q;
#pragma unroll
        for (int ni = 0; ni < 8; ni++) {
            int c0 = n0 + (wn8 + ni) * 8 + s * 2;
#pragma unroll
            for (int rr = 0; rr < 2; rr++) {
                int r = r0 + rr * 8;
                float bv = bias[r];
                *reinterpret_cast<float2*>(&Cp[(size_t)r * ldc + c0]) =
                    make_float2(acc[mi][ni][rr * 2] + bv, acc[mi][ni][rr * 2 + 1] + bv);
            }
        }
    }
}

// ---------------------------------------------------------------------------
// Final GEMM: A = g_mid KPERM row-major (LDS.64 fragments), B = Wo fragment-
// major (LDS.128). 3-stage pipeline. C[r][o] = sum_c A[r][c]*B[o][c] + bias[o].
// ---------------------------------------------------------------------------
#define FIN_A_STG 5120                 // 128*40 floats
#define FIN_B_OFF (3 * FIN_A_STG)      // float offset of B slabs
#define FIN_SMEM ((3 * FIN_A_STG + 3 * 4096) * 4)

__global__ __launch_bounds__(256, 2) void gemm_fin(
    const float* __restrict__ A, size_t sAb,
    const float* __restrict__ B,
    const float* __restrict__ bias,
    float* __restrict__ C, size_t sCb, int ldc)
{
    extern __shared__ __align__(16) float sm[];
    const uint32_t smb = smem_u32(sm);
    const int b  = blockIdx.z;
    const int n0 = blockIdx.x * 128;
    const int m0 = blockIdx.y * 128;
    const float* Ap = A + (size_t)b * sAb + (size_t)m0 * KDIM;
    const float* Bg = B + (size_t)(n0 >> 7) * 65536;

    const int t = threadIdx.x, lane = t & 31, w = t >> 5;
    const int wm = (w & 3) * 32;
    const int wn8 = (w >> 2) * 8;
    const int q = lane >> 2, s = lane & 3;

    float acc[2][8][4] = {};

    auto fill = [&](int buf, int it) {
        const int ko = it * 32;
#pragma unroll
        for (int i = 0; i < 4; i++) {
            int id = t + i * 256;
            int r = id >> 3, c4 = (id & 7) * 4;
            CP16(smb + (buf * FIN_A_STG + r * 40 + c4) * 4,
                 Ap + (size_t)r * KDIM + ko + c4);
        }
        const float* sb = Bg + (ko >> 4) * 2048;
        uint32_t db = smb + (FIN_B_OFF + buf * 4096) * 4 + t * 16;
#pragma unroll
        for (int i = 0; i < 4; i++) CP16(db + i * 4096, sb + t * 4 + i * 1024);
        CP_COMMIT();
    };

    fill(0, 0); fill(1, 1);
    int fb = 2;

    for (int it = 0; it < 16; it++) {
        const int buf = it % 3;
        __syncthreads();
        if (it <= 13) { fill(fb, it + 2); fb = (fb == 2) ? 0 : fb + 1; CP_WAIT2(); }
        else if (it == 14) CP_WAIT1();
        else CP_WAIT0();
        __syncthreads();

        const float* Ab = sm + buf * FIN_A_STG;
        const float4* Bt = reinterpret_cast<const float4*>(sm + FIN_B_OFF) + buf * 1024;
#pragma unroll
        for (int kp = 0; kp < 2; kp++) {
            uint32_t af[2][2][4];
#pragma unroll
            for (int kkl = 0; kkl < 2; kkl++) {
                const int kc = (kp * 2 + kkl) * 8 + s * 2;
#pragma unroll
                for (int mi = 0; mi < 2; mi++) {
                    const int rb = wm + mi * 16 + q;
                    float2 a02 = *reinterpret_cast<const float2*>(&Ab[rb * 40 + kc]);
                    float2 a13 = *reinterpret_cast<const float2*>(&Ab[(rb + 8) * 40 + kc]);
                    af[mi][kkl][0] = __float_as_uint(a02.x);
                    af[mi][kkl][1] = __float_as_uint(a13.x);
                    af[mi][kkl][2] = __float_as_uint(a02.y);
                    af[mi][kkl][3] = __float_as_uint(a13.y);
                }
            }
#pragma unroll
            for (int nh = 0; nh < 2; nh++) {
                float4 bf[4];
#pragma unroll
                for (int nj = 0; nj < 4; nj++)
                    bf[nj] = Bt[(kp * 16 + wn8 + nh * 4 + nj) * 32 + lane];
#pragma unroll
                for (int kkl = 0; kkl < 2; kkl++)
#pragma unroll
                    for (int nj = 0; nj < 4; nj++) {
                        const int ni = nh * 4 + nj;
                        uint32_t b0 = __float_as_uint(kkl ? bf[nj].z : bf[nj].x);
                        uint32_t b1 = __float_as_uint(kkl ? bf[nj].w : bf[nj].y);
#pragma unroll
                        for (int mi = 0; mi < 2; mi++)
                            MMA_TF32(acc[mi][ni], af[mi][kkl][0], af[mi][kkl][1],
                                     af[mi][kkl][2], af[mi][kkl][3], b0, b1);
                    }
            }
        }
    }

    float* Cp = C + (size_t)b * sCb;
#pragma unroll
    for (int mi = 0; mi < 2; mi++) {
        int r0 = m0 + wm + mi * 16 + q;
#pragma unroll
        for (int ni = 0; ni < 8; ni++) {
            int c0 = n0 + (wn8 + ni) * 8 + s * 2;
#pragma unroll
            for (int rr = 0; rr < 2; rr++) {
                int r = r0 + rr * 8;
                *reinterpret_cast<float2*>(&Cp[(size_t)r * ldc + c0]) =
                    make_float2(acc[mi][ni][rr * 2] + bias[c0],
                                acc[mi][ni][rr * 2 + 1] + bias[c0 + 1]);
            }
        }
    }
}

// ---------------------------------------------------------------- pre-passes
__global__ void round_w(const float* __restrict__ Wq, const float* __restrict__ bq,
                        const float* __restrict__ Wk, const float* __restrict__ bk,
                        const float* __restrict__ Wv, const float* __restrict__ Wo) {
    uint32_t idx = blockIdx.x * 256 + threadIdx.x;
    int job = blockIdx.y;
    if (job == 0) {
        if (idx < NC * NC) g_Wv32[idxA(idx >> 9, idx & 511)] = f2tf(Wv[idx]);
    } else if (job == 1) {
        if (idx < NC * NC) g_Wo32[idxB(idx >> 9, idx & 511)] = f2tf(Wo[idx]);
    } else {
        if (idx < 64 * NC) {
            uint32_t m = idx >> 9, c = idx & 511;
            g_Wqk[idxA(m, c)]      = f2tf(Wq[idx]);
            g_Wqk[idxA(m + 64, c)] = f2tf(Wk[idx]);
        }
        if (idx < 64) { g_bqk[idx] = bq[idx]; g_bqk[64 + idx] = bk[idx]; }
    }
}

__global__ __launch_bounds__(256) void transpose_x(const float* __restrict__ x) {
    __shared__ float ts[32][33];
    const int b = blockIdx.z;
    const int hw0 = blockIdx.x * 32, c0 = blockIdx.y * 32;
    const int tx = threadIdx.x, ty = threadIdx.y;
    const float* xb = x + (size_t)b * NC * NHW;
#pragma unroll
    for (int i = 0; i < 4; i++) {
        int r = ty + i * 8;
        ts[r][tx] = xb[(size_t)(c0 + r) * NHW + hw0 + tx];
    }
    __syncthreads();
    float* ob = g_xT + (size_t)b * NHW * NC;
#pragma unroll
    for (int i = 0; i < 4; i++) {
        int r = ty + i * 8;
        ob[idxB(hw0 + r, c0 + tx)] = f2tf(ts[tx][r]);
    }
}

// ---------------------------------------------------------------- scores+softmax
__global__ __launch_bounds__(256) void scores_kernel() {
    const int bn = blockIdx.x;
    const int b = bn >> 3, n = bn & 7;
    const float* qb = g_qk + (size_t)b * 128 * NHW + (size_t)n * 32768;
    const float* kb = qb + 64 * NHW;

    __shared__ float Qs[64][65];
    __shared__ float Ks[64][65];

    const int t = threadIdx.x;
    const int te = (t & 15) * 4;
    const int td = (t >> 4) * 4;

    float acc[4][4] = {};

    for (int lc = 0; lc < 8; lc++) {
#pragma unroll
        for (int i = 0; i < 16; i++) {
            int id = t + i * 256;
            Qs[id >> 6][id & 63] = qb[lc * 4096 + id];
            Ks[id >> 6][id & 63] = kb[lc * 4096 + id];
        }
        __syncthreads();
#pragma unroll 8
        for (int li = 0; li < 64; li++) {
            float a[4], bb[4];
#pragma unroll
            for (int i = 0; i < 4; i++) a[i] = Qs[li][td + i];
#pragma unroll
            for (int j = 0; j < 4; j++) bb[j] = Ks[li][te + j];
#pragma unroll
            for (int i = 0; i < 4; i++)
#pragma unroll
                for (int j = 0; j < 4; j++)
                    acc[i][j] = fmaf(a[i], bb[j], acc[i][j]);
        }
        __syncthreads();
    }

#pragma unroll
    for (int i = 0; i < 4; i++)
#pragma unroll
        for (int j = 0; j < 4; j++)
            Qs[td + i][te + j] = acc[i][j] * 0.125f;
    __syncthreads();

    if (t < 64) {
        float m = -1e30f;
        for (int e = 0; e < 64; e++) m = fmaxf(m, Qs[t][e]);
        float sum = 0.f;
        for (int e = 0; e < 64; e++) { float v2 = __expf(Qs[t][e] - m); Qs[t][e] = v2; sum += v2; }
        float inv = 1.f / sum;
        for (int e = 0; e < 64; e++) Qs[t][e] *= inv;
    }
    __syncthreads();

    float* ab = g_attn + (size_t)bn * 4096;
#pragma unroll
    for (int i = 0; i < 16; i++) {
        int id = t + i * 256;
        ab[id] = Qs[id >> 6][id & 63];
    }
}

// ---------------------------------------------------------------- attn @ v (TC)
// Split-precision tf32 (3-pass: Vhi*Ahi + Vhi*Alo + Vlo*Ahi) -> ~fp32 accurate.
// Block = (chpair, n, b): 2 V-channels. C_c[h][w'] = sum_e V_c[h][e]*A[w'][e].
// Warp w: channel w&1, m-block (w>>1)*16. Output -> g_mid KPERM row-major.
#define AVS 4352   // 64*68 floats per tile
#define ATTNV_SMEM (3 * AVS * 4)

__global__ __launch_bounds__(256) void attnv_tc() {
    extern __shared__ __align__(16) float sm[];
    const uint32_t smb = smem_u32(sm);
    const int d2 = blockIdx.x * 2;
    const int n  = blockIdx.y;
    const int b  = blockIdx.z;
    const int t = threadIdx.x, lane = t & 31, w = t >> 5;
    const int q = lane >> 2, s = lane & 3;

    {   // fill: attn tile + 2 V channel tiles (contiguous 16KB slabs)
        const float* srcs[3] = {
            g_attn + ((size_t)b * 8 + n) * 4096,
            g_v + ((size_t)b * NC + n * 64 + d2) * (size_t)NHW,
            g_v + ((size_t)b * NC + n * 64 + d2 + 1) * (size_t)NHW };
#pragma unroll
        for (int tile = 0; tile < 3; tile++) {
#pragma unroll
            for (int i = 0; i < 4; i++) {
                int unit = t + i * 256;          // 1024 units of 4 floats
                int row = unit >> 4, ch4 = (unit & 15) * 4;
                CP16(smb + (tile * AVS + row * 68 + ch4) * 4,
                     srcs[tile] + row * 64 + ch4);
            }
        }
        CP_COMMIT(); CP_WAIT0();
    }
    __syncthreads();

    const float* At = sm;                        // attn [w'][e]
    const float* Vt = sm + AVS + (w & 1) * AVS;  // V channel [h][e]
    const int rbase = (w >> 1) * 16;

    float acc[8][4] = {};
#pragma unroll
    for (int kb = 0; kb < 8; kb++) {
        const int k8 = kb * 8;
        const int rb = rbase + q;
        float av[4];
        av[0] = Vt[rb * 68 + k8 + s];
        av[1] = Vt[(rb + 8) * 68 + k8 + s];
        av[2] = Vt[rb * 68 + k8 + s + 4];
        av[3] = Vt[(rb + 8) * 68 + k8 + s + 4];
        uint32_t ah[4], al[4];
#pragma unroll
        for (int i = 0; i < 4; i++) {
            float h = f2tf(av[i]);
            ah[i] = __float_as_uint(h);
            al[i] = __float_as_uint(f2tf(av[i] - h));
        }
#pragma unroll
        for (int nb = 0; nb < 8; nb++) {
            float bv0 = At[(nb * 8 + q) * 68 + k8 + s];
            float bv1 = At[(nb * 8 + q) * 68 + k8 + s + 4];
            float bh0f = f2tf(bv0), bh1f = f2tf(bv1);
            uint32_t bh0 = __float_as_uint(bh0f), bh1 = __float_as_uint(bh1f);
            uint32_t bl0 = __float_as_uint(f2tf(bv0 - bh0f));
            uint32_t bl1 = __float_as_uint(f2tf(bv1 - bh1f));
            MMA_TF32(acc[nb], ah[0], ah[1], ah[2], ah[3], bh0, bh1);
            MMA_TF32(acc[nb], ah[0], ah[1], ah[2], ah[3], bl0, bl1);
            MMA_TF32(acc[nb], al[0], al[1], al[2], al[3], bh0, bh1);
        }
    }

    const int ch_out = (d2 + (w & 1)) * 8 + n;
    float* mb = g_mid + (size_t)b * NC * NHW;
#pragma unroll
    for (int nb = 0; nb < 8; nb++)
#pragma unroll
        for (int rr = 0; rr < 2; rr++) {
            const int h = rbase + q + rr * 8;
#pragma unroll
            for (int j = 0; j < 2; j++) {
                uint32_t o = ch_out * 4096 + h * 64 + nb * 8 + s * 2 + j;
                mb[(o & ~7u) | KPERM(o & 7u)] = f2tf(acc[nb][rr * 2 + j]);
            }
        }
}

// ---------------------------------------------------------------- launch
extern "C" void kernel_launch(void* const* d_in, const int* in_sizes, int n_in,
                              void* d_out, int out_size) {
    (void)in_sizes; (void)n_in; (void)out_size;
    const float* x  = (const float*)d_in[0];
    const float* Wq = (const float*)d_in[1];
    const float* bq = (const float*)d_in[2];
    const float* Wk = (const float*)d_in[3];
    const float* bk = (const float*)d_in[4];
    const float* Wv = (const float*)d_in[5];
    const float* bv = (const float*)d_in[6];
    const float* Wo = (const float*)d_in[7];
    const float* bo = (const float*)d_in[8];
    float* out = (float*)d_out;

    cudaFuncSetAttribute(gemm_proj, cudaFuncAttributeMaxDynamicSharedMemorySize, PROJ_SMEM);
    cudaFuncSetAttribute(gemm_fin,  cudaFuncAttributeMaxDynamicSharedMemorySize, FIN_SMEM);
    cudaFuncSetAttribute(attnv_tc,  cudaFuncAttributeMaxDynamicSharedMemorySize, ATTNV_SMEM);

    float *xT, *qk_p, *v_p, *mid_p, *Wqk_p, *Wv_p, *Wo_p, *bqk_p;
    cudaGetSymbolAddress((void**)&xT,    g_xT);
    cudaGetSymbolAddress((void**)&qk_p,  g_qk);
    cudaGetSymbolAddress((void**)&v_p,   g_v);
    cudaGetSymbolAddress((void**)&mid_p, g_mid);
    cudaGetSymbolAddress((void**)&Wqk_p, g_Wqk);
    cudaGetSymbolAddress((void**)&Wv_p,  g_Wv32);
    cudaGetSymbolAddress((void**)&Wo_p,  g_Wo32);
    cudaGetSymbolAddress((void**)&bqk_p, g_bqk);

    round_w<<<dim3(1024, 3), 256>>>(Wq, bq, Wk, bk, Wv, Wo);
    transpose_x<<<dim3(128, 16, 16), dim3(32, 8)>>>(x);

    // q/k projection: C[128 x 4096] per b
    gemm_proj<<<dim3(32, 1, NB), 256, PROJ_SMEM>>>(
        Wqk_p, 0, xT, (size_t)NHW * NC, bqk_p,
        qk_p, (size_t)128 * NHW, NHW);
    // v projection: C[512 x 4096] per b
    gemm_proj<<<dim3(32, 4, NB), 256, PROJ_SMEM>>>(
        Wv_p, 0, xT, (size_t)NHW * NC, bv,
        v_p, (size_t)NC * NHW, NHW);

    scores_kernel<<<128, 256>>>();
    attnv_tc<<<dim3(32, 8, NB), 256, ATTNV_SMEM>>>();

    // final linear: C[4096 x 512] per b
    gemm_fin<<<dim3(4, 32, NB), 256, FIN_SMEM>>>(
        mid_p, (size_t)NC * NHW, Wo_p, bo,
        out, (size_t)NC * NHW, NC);
}

// round 13
// speedup vs baseline: 3.8452x; 1.0395x over previous
#include <cuda_runtime.h>
#include <cstdint>

#define NB 16
#define NC 512
#define NHW 4096
#define KDIM 512

// ---------------------------------------------------------------- scratch
__device__ float g_xT[(size_t)NB * NHW * NC];    // B-fragment layout (n=hw,k=c)
__device__ float g_qk[(size_t)NB * 128 * NHW];   // row-major
__device__ float g_v[(size_t)NB * NC * NHW];     // row-major
__device__ float g_attn[(size_t)NB * 8 * 64 * 64];
__device__ float g_mid[(size_t)NB * NC * NHW];   // A-fragment layout, tf32
__device__ float g_Wqk[128 * NC];                // A-fragment layout
__device__ float g_Wv32[NC * NC];                // A-fragment layout
__device__ float g_Wo32[NC * NC];                // B-fragment layout
__device__ float g_bqk[128];

__device__ __forceinline__ float f2tf(float f) {
    uint32_t o; asm("cvt.rna.tf32.f32 %0, %1;" : "=r"(o) : "f"(f));
    return __uint_as_float(o);
}

// A-fragment-major: 16m x 8k blocks, ordered [M128][kb8][mb16][lane][slot]
__device__ __forceinline__ uint32_t idxA(uint32_t m, uint32_t k) {
    return ((((m >> 7) * (KDIM / 8) + (k >> 3)) * 8 + ((m & 127) >> 4)) * 32
            + (((m & 7) << 2) | (k & 3))) * 4
           + (((m >> 3) & 1) | (((k >> 2) & 1) << 1));
}
// B-fragment-major: 8n x 16k blocks, ordered [N128][kb16][nb8][lane][slot]
__device__ __forceinline__ uint32_t idxB(uint32_t n, uint32_t k) {
    return ((((n >> 7) * (KDIM / 16) + (k >> 4)) * 16 + ((n & 127) >> 3)) * 32
            + (((n & 7) << 2) | (k & 3))) * 4
           + ((k >> 2) & 3);
}

#define CP16(dst, src) asm volatile("cp.async.cg.shared.global [%0], [%1], 16;" :: "r"(dst), "l"(src) : "memory")
#define CP_COMMIT()    asm volatile("cp.async.commit_group;" ::: "memory")
#define CP_WAIT2()     asm volatile("cp.async.wait_group 2;" ::: "memory")
#define CP_WAIT1()     asm volatile("cp.async.wait_group 1;" ::: "memory")
#define CP_WAIT0()     asm volatile("cp.async.wait_group 0;" ::: "memory")

__device__ __forceinline__ uint32_t smem_u32(const void* p) {
    uint32_t a;
    asm("{ .reg .u64 t; cvta.to.shared.u64 t, %1; cvt.u32.u64 %0, t; }" : "=r"(a) : "l"(p));
    return a;
}

#define MMA_TF32(acc, a0, a1, a2, a3, b0, b1) \
    asm volatile("mma.sync.aligned.m16n8k8.row.col.f32.tf32.tf32.f32 " \
        "{%0,%1,%2,%3},{%4,%5,%6,%7},{%8,%9},{%0,%1,%2,%3};" \
        : "+f"((acc)[0]), "+f"((acc)[1]), "+f"((acc)[2]), "+f"((acc)[3]) \
        : "r"(a0), "r"(a1), "r"(a2), "r"(a3), "r"(b0), "r"(b1))

// ---------------------------------------------------------------------------
// Big-tile GEMM: CTA 256m x 128n, warp tile 64x64 (8 warps: 4m x 2n), BK=32,
// 3-stage cp.async. Both operands fragment-major. 4 MMAs per LDS.128.
// C[m][n] = sum_k A[m][k]*B[n][k] + bias (m if !BIASN else n).
// ---------------------------------------------------------------------------
#define BIG_STAGE_B 49152                 // A 32KB + B 16KB
#define BIG_SMEM (3 * BIG_STAGE_B)

template <bool BIASN>
__global__ __launch_bounds__(256, 1) void gemm_big(
    const float* __restrict__ A, size_t sAb,
    const float* __restrict__ B, size_t sBb,
    const float* __restrict__ bias,
    float* __restrict__ C, size_t sCb, int ldc)
{
    extern __shared__ __align__(16) float sm[];
    const uint32_t smb = smem_u32(sm);
    const int b  = blockIdx.z;
    const int n0 = blockIdx.x * 128;
    const int m0 = blockIdx.y * 256;
    const float* Ag = A + (size_t)b * sAb + (size_t)(m0 >> 7) * 65536;
    const float* Bg = B + (size_t)b * sBb + (size_t)(n0 >> 7) * 65536;

    const int t = threadIdx.x, lane = t & 31, w = t >> 5;
    const int wy = w & 3, wx = w >> 2;
    const int blk = wy >> 1, mb0 = (wy & 1) * 4;
    const int q = lane >> 2, s = lane & 3;

    float acc[4][8][4] = {};

    auto fill = [&](int buf, int it) {
        const int ko = it * 32;
        const float* a0 = Ag + (ko >> 3) * 1024;           // M128-block 0 slab
        const float* a1 = a0 + 65536;                      // M128-block 1 slab
        const float* bb = Bg + (ko >> 4) * 2048;
        uint32_t d = smb + buf * BIG_STAGE_B + t * 16;
#pragma unroll
        for (int i = 0; i < 4; i++) CP16(d + i * 4096,         a0 + t * 4 + i * 1024);
#pragma unroll
        for (int i = 0; i < 4; i++) CP16(d + 16384 + i * 4096, a1 + t * 4 + i * 1024);
#pragma unroll
        for (int i = 0; i < 4; i++) CP16(d + 32768 + i * 4096, bb + t * 4 + i * 1024);
        CP_COMMIT();
    };

    fill(0, 0); fill(1, 1);
    int fb = 2;

    for (int it = 0; it < 16; it++) {
        const int buf = it % 3;
        __syncthreads();
        if (it <= 13) { fill(fb, it + 2); fb = (fb == 2) ? 0 : fb + 1; CP_WAIT2(); }
        else if (it == 14) CP_WAIT1();
        else CP_WAIT0();
        __syncthreads();

        const float4* At = reinterpret_cast<const float4*>(sm) + buf * 3072;
        const float4* Bt = At + 2048;
#pragma unroll
        for (int kp = 0; kp < 2; kp++) {
            float4 bf[8];
#pragma unroll
            for (int nj = 0; nj < 8; nj++)
                bf[nj] = Bt[(kp * 16 + wx * 8 + nj) * 32 + lane];
#pragma unroll
            for (int kkl = 0; kkl < 2; kkl++) {
                const int kb = kp * 2 + kkl;
                float4 af[4];
#pragma unroll
                for (int mi = 0; mi < 4; mi++)
                    af[mi] = At[blk * 1024 + (kb * 8 + mb0 + mi) * 32 + lane];
#pragma unroll
                for (int nj = 0; nj < 8; nj++) {
                    uint32_t b0 = __float_as_uint(kkl ? bf[nj].z : bf[nj].x);
                    uint32_t b1 = __float_as_uint(kkl ? bf[nj].w : bf[nj].y);
#pragma unroll
                    for (int mi = 0; mi < 4; mi++)
                        MMA_TF32(acc[mi][nj],
                                 __float_as_uint(af[mi].x), __float_as_uint(af[mi].y),
                                 __float_as_uint(af[mi].z), __float_as_uint(af[mi].w),
                                 b0, b1);
                }
            }
        }
    }

    float* Cp = C + (size_t)b * sCb;
#pragma unroll
    for (int mi = 0; mi < 4; mi++) {
        int r0 = m0 + (wy * 4 + mi) * 16 + q;
#pragma unroll
        for (int nj = 0; nj < 8; nj++) {
            int c0 = n0 + wx * 64 + nj * 8 + s * 2;
#pragma unroll
            for (int rr = 0; rr < 2; rr++) {
                int r = r0 + rr * 8;
                float v0 = acc[mi][nj][rr * 2], v1 = acc[mi][nj][rr * 2 + 1];
                if (BIASN) { v0 += bias[c0]; v1 += bias[c0 + 1]; }
                else       { float bv = bias[r]; v0 += bv; v1 += bv; }
                *reinterpret_cast<float2*>(&Cp[(size_t)r * ldc + c0]) = make_float2(v0, v1);
            }
        }
    }
}

// ---------------------------------------------------------------------------
// 128x128 GEMM (for M=128 qk projection), proven R6/R12 path.
// ---------------------------------------------------------------------------
#define PROJ_SMEM (3 * 32768)

__global__ __launch_bounds__(256, 2) void gemm_proj(
    const float* __restrict__ A, size_t sAb,
    const float* __restrict__ B, size_t sBb,
    const float* __restrict__ bias,
    float* __restrict__ C, size_t sCb, int ldc)
{
    extern __shared__ __align__(16) float sm[];
    const uint32_t smb = smem_u32(sm);
    const int b  = blockIdx.z;
    const int n0 = blockIdx.x * 128;
    const int m0 = blockIdx.y * 128;
    const float* Ag = A + (size_t)b * sAb + (size_t)(m0 >> 7) * 65536;
    const float* Bg = B + (size_t)b * sBb + (size_t)(n0 >> 7) * 65536;

    const int t = threadIdx.x, lane = t & 31, w = t >> 5;
    const int wm16 = (w & 3) * 2;
    const int wn8  = (w >> 2) * 8;
    const int q = lane >> 2, s = lane & 3;

    float acc[2][8][4] = {};

    auto fill = [&](int buf, int it) {
        const int ko = it * 32;
        const float* sa = Ag + (ko >> 3) * 1024;
        const float* sb = Bg + (ko >> 4) * 2048;
        uint32_t da = smb + buf * 32768 + t * 16;
#pragma unroll
        for (int i = 0; i < 4; i++) CP16(da + i * 4096, sa + t * 4 + i * 1024);
#pragma unroll
        for (int i = 0; i < 4; i++) CP16(da + 16384 + i * 4096, sb + t * 4 + i * 1024);
        CP_COMMIT();
    };

    fill(0, 0); fill(1, 1);
    int fb = 2;

    for (int it = 0; it < 16; it++) {
        const int buf = it % 3;
        __syncthreads();
        if (it <= 13) { fill(fb, it + 2); fb = (fb == 2) ? 0 : fb + 1; CP_WAIT2(); }
        else if (it == 14) CP_WAIT1();
        else CP_WAIT0();
        __syncthreads();

        const float4* At = reinterpret_cast<const float4*>(sm) + buf * 2048;
        const float4* Bt = At + 1024;
#pragma unroll
        for (int kp = 0; kp < 2; kp++) {
            float4 af[2][2];
#pragma unroll
            for (int kkl = 0; kkl < 2; kkl++)
#pragma unroll
                for (int mi = 0; mi < 2; mi++)
                    af[mi][kkl] = At[((kp * 2 + kkl) * 8 + wm16 + mi) * 32 + lane];
#pragma unroll
            for (int nh = 0; nh < 2; nh++) {
                float4 bf[4];
#pragma unroll
                for (int nj = 0; nj < 4; nj++)
                    bf[nj] = Bt[(kp * 16 + wn8 + nh * 4 + nj) * 32 + lane];
#pragma unroll
                for (int kkl = 0; kkl < 2; kkl++)
#pragma unroll
                    for (int nj = 0; nj < 4; nj++) {
                        const int ni = nh * 4 + nj;
                        uint32_t b0 = __float_as_uint(kkl ? bf[nj].z : bf[nj].x);
                        uint32_t b1 = __float_as_uint(kkl ? bf[nj].w : bf[nj].y);
#pragma unroll
                        for (int mi = 0; mi < 2; mi++)
                            MMA_TF32(acc[mi][ni],
                                     __float_as_uint(af[mi][kkl].x),
                                     __float_as_uint(af[mi][kkl].y),
                                     __float_as_uint(af[mi][kkl].z),
                                     __float_as_uint(af[mi][kkl].w), b0, b1);
                    }
            }
        }
    }

    float* Cp = C + (size_t)b * sCb;
#pragma unroll
    for (int mi = 0; mi < 2; mi++) {
        int r0 = m0 + (wm16 + mi) * 16 + q;
#pragma unroll
        for (int ni = 0; ni < 8; ni++) {
            int c0 = n0 + (wn8 + ni) * 8 + s * 2;
#pragma unroll
            for (int rr = 0; rr < 2; rr++) {
                int r = r0 + rr * 8;
                float bv = bias[r];
                *reinterpret_cast<float2*>(&Cp[(size_t)r * ldc + c0]) =
                    make_float2(acc[mi][ni][rr * 2] + bv, acc[mi][ni][rr * 2 + 1] + bv);
            }
        }
    }
}

// ---------------------------------------------------------------- pre-passes
__global__ void round_w(const float* __restrict__ Wq, const float* __restrict__ bq,
                        const float* __restrict__ Wk, const float* __restrict__ bk,
                        const float* __restrict__ Wv, const float* __restrict__ Wo) {
    uint32_t idx = blockIdx.x * 256 + threadIdx.x;
    int job = blockIdx.y;
    if (job == 0) {
        if (idx < NC * NC) g_Wv32[idxA(idx >> 9, idx & 511)] = f2tf(Wv[idx]);
    } else if (job == 1) {
        if (idx < NC * NC) g_Wo32[idxB(idx >> 9, idx & 511)] = f2tf(Wo[idx]);
    } else {
        if (idx < 64 * NC) {
            uint32_t m = idx >> 9, c = idx & 511;
            g_Wqk[idxA(m, c)]      = f2tf(Wq[idx]);
            g_Wqk[idxA(m + 64, c)] = f2tf(Wk[idx]);
        }
        if (idx < 64) { g_bqk[idx] = bq[idx]; g_bqk[64 + idx] = bk[idx]; }
    }
}

__global__ __launch_bounds__(256) void transpose_x(const float* __restrict__ x) {
    __shared__ float ts[32][33];
    const int b = blockIdx.z;
    const int hw0 = blockIdx.x * 32, c0 = blockIdx.y * 32;
    const int tx = threadIdx.x, ty = threadIdx.y;
    const float* xb = x + (size_t)b * NC * NHW;
#pragma unroll
    for (int i = 0; i < 4; i++) {
        int r = ty + i * 8;
        ts[r][tx] = xb[(size_t)(c0 + r) * NHW + hw0 + tx];
    }
    __syncthreads();
    float* ob = g_xT + (size_t)b * NHW * NC;
#pragma unroll
    for (int i = 0; i < 4; i++) {
        int r = ty + i * 8;
        ob[idxB(hw0 + r, c0 + tx)] = f2tf(ts[tx][r]);
    }
}

// ---------------------------------------------------------------- scores+softmax
__global__ __launch_bounds__(256) void scores_kernel() {
    const int bn = blockIdx.x;
    const int b = bn >> 3, n = bn & 7;
    const float* qb = g_qk + (size_t)b * 128 * NHW + (size_t)n * 32768;
    const float* kb = qb + 64 * NHW;

    __shared__ float Qs[64][65];
    __shared__ float Ks[64][65];

    const int t = threadIdx.x;
    const int te = (t & 15) * 4;
    const int td = (t >> 4) * 4;

    float acc[4][4] = {};

    for (int lc = 0; lc < 8; lc++) {
#pragma unroll
        for (int i = 0; i < 16; i++) {
            int id = t + i * 256;
            Qs[id >> 6][id & 63] = qb[lc * 4096 + id];
            Ks[id >> 6][id & 63] = kb[lc * 4096 + id];
        }
        __syncthreads();
#pragma unroll 8
        for (int li = 0; li < 64; li++) {
            float a[4], bb[4];
#pragma unroll
            for (int i = 0; i < 4; i++) a[i] = Qs[li][td + i];
#pragma unroll
            for (int j = 0; j < 4; j++) bb[j] = Ks[li][te + j];
#pragma unroll
            for (int i = 0; i < 4; i++)
#pragma unroll
                for (int j = 0; j < 4; j++)
                    acc[i][j] = fmaf(a[i], bb[j], acc[i][j]);
        }
        __syncthreads();
    }

#pragma unroll
    for (int i = 0; i < 4; i++)
#pragma unroll
        for (int j = 0; j < 4; j++)
            Qs[td + i][te + j] = acc[i][j] * 0.125f;
    __syncthreads();

    if (t < 64) {
        float m = -1e30f;
        for (int e = 0; e < 64; e++) m = fmaxf(m, Qs[t][e]);
        float sum = 0.f;
        for (int e = 0; e < 64; e++) { float v2 = __expf(Qs[t][e] - m); Qs[t][e] = v2; sum += v2; }
        float inv = 1.f / sum;
        for (int e = 0; e < 64; e++) Qs[t][e] *= inv;
    }
    __syncthreads();

    float* ab = g_attn + (size_t)bn * 4096;
#pragma unroll
    for (int i = 0; i < 16; i++) {
        int id = t + i * 256;
        ab[id] = Qs[id >> 6][id & 63];
    }
}

// ---------------------------------------------------------------- attn @ v (TC)
// Split-precision tf32 (Vhi*Ahi + Vhi*Alo + Vlo*Ahi). Output -> g_mid in
// A-fragment layout (idxA over r = flat>>9, k = flat&511).
#define AVS 4352   // 64*68 floats per tile
#define ATTNV_SMEM (3 * AVS * 4)

__global__ __launch_bounds__(256) void attnv_tc() {
    extern __shared__ __align__(16) float sm[];
    const uint32_t smb = smem_u32(sm);
    const int d2 = blockIdx.x * 2;
    const int n  = blockIdx.y;
    const int b  = blockIdx.z;
    const int t = threadIdx.x, lane = t & 31, w = t >> 5;
    const int q = lane >> 2, s = lane & 3;

    {
        const float* srcs[3] = {
            g_attn + ((size_t)b * 8 + n) * 4096,
            g_v + ((size_t)b * NC + n * 64 + d2) * (size_t)NHW,
            g_v + ((size_t)b * NC + n * 64 + d2 + 1) * (size_t)NHW };
#pragma unroll
        for (int tile = 0; tile < 3; tile++) {
#pragma unroll
            for (int i = 0; i < 4; i++) {
                int unit = t + i * 256;
                int row = unit >> 4, ch4 = (unit & 15) * 4;
                CP16(smb + (tile * AVS + row * 68 + ch4) * 4,
                     srcs[tile] + row * 64 + ch4);
            }
        }
        CP_COMMIT(); CP_WAIT0();
    }
    __syncthreads();

    const float* At = sm;
    const float* Vt = sm + AVS + (w & 1) * AVS;
    const int rbase = (w >> 1) * 16;

    float acc[8][4] = {};
#pragma unroll
    for (int kb = 0; kb < 8; kb++) {
        const int k8 = kb * 8;
        const int rb = rbase + q;
        float av[4];
        av[0] = Vt[rb * 68 + k8 + s];
        av[1] = Vt[(rb + 8) * 68 + k8 + s];
        av[2] = Vt[rb * 68 + k8 + s + 4];
        av[3] = Vt[(rb + 8) * 68 + k8 + s + 4];
        uint32_t ah[4], al[4];
#pragma unroll
        for (int i = 0; i < 4; i++) {
            float h = f2tf(av[i]);
            ah[i] = __float_as_uint(h);
            al[i] = __float_as_uint(f2tf(av[i] - h));
        }
#pragma unroll
        for (int nb = 0; nb < 8; nb++) {
            float bv0 = At[(nb * 8 + q) * 68 + k8 + s];
            float bv1 = At[(nb * 8 + q) * 68 + k8 + s + 4];
            float bh0f = f2tf(bv0), bh1f = f2tf(bv1);
            uint32_t bh0 = __float_as_uint(bh0f), bh1 = __float_as_uint(bh1f);
            uint32_t bl0 = __float_as_uint(f2tf(bv0 - bh0f));
            uint32_t bl1 = __float_as_uint(f2tf(bv1 - bh1f));
            MMA_TF32(acc[nb], ah[0], ah[1], ah[2], ah[3], bh0, bh1);
            MMA_TF32(acc[nb], ah[0], ah[1], ah[2], ah[3], bl0, bl1);
            MMA_TF32(acc[nb], al[0], al[1], al[2], al[3], bh0, bh1);
        }
    }

    const int ch_out = (d2 + (w & 1)) * 8 + n;
    float* mb = g_mid + (size_t)b * NC * NHW;
#pragma unroll
    for (int nb = 0; nb < 8; nb++)
#pragma unroll
        for (int rr = 0; rr < 2; rr++) {
            const int h = rbase + q + rr * 8;
            const uint32_t r = ch_out * 8 + (h >> 3);
            const uint32_t kc0 = (h & 7) * 64 + nb * 8 + s * 2;
#pragma unroll
            for (int j = 0; j < 2; j++)
                mb[idxA(r, kc0 + j)] = f2tf(acc[nb][rr * 2 + j]);
        }
}

// ---------------------------------------------------------------- launch
extern "C" void kernel_launch(void* const* d_in, const int* in_sizes, int n_in,
                              void* d_out, int out_size) {
    (void)in_sizes; (void)n_in; (void)out_size;
    const float* x  = (const float*)d_in[0];
    const float* Wq = (const float*)d_in[1];
    const float* bq = (const float*)d_in[2];
    const float* Wk = (const float*)d_in[3];
    const float* bk = (const float*)d_in[4];
    const float* Wv = (const float*)d_in[5];
    const float* bv = (const float*)d_in[6];
    const float* Wo = (const float*)d_in[7];
    const float* bo = (const float*)d_in[8];
    float* out = (float*)d_out;

    cudaFuncSetAttribute(gemm_proj, cudaFuncAttributeMaxDynamicSharedMemorySize, PROJ_SMEM);
    cudaFuncSetAttribute(gemm_big<false>, cudaFuncAttributeMaxDynamicSharedMemorySize, BIG_SMEM);
    cudaFuncSetAttribute(gemm_big<true>,  cudaFuncAttributeMaxDynamicSharedMemorySize, BIG_SMEM);
    cudaFuncSetAttribute(attnv_tc,  cudaFuncAttributeMaxDynamicSharedMemorySize, ATTNV_SMEM);

    float *xT, *qk_p, *v_p, *mid_p, *Wqk_p, *Wv_p, *Wo_p, *bqk_p;
    cudaGetSymbolAddress((void**)&xT,    g_xT);
    cudaGetSymbolAddress((void**)&qk_p,  g_qk);
    cudaGetSymbolAddress((void**)&v_p,   g_v);
    cudaGetSymbolAddress((void**)&mid_p, g_mid);
    cudaGetSymbolAddress((void**)&Wqk_p, g_Wqk);
    cudaGetSymbolAddress((void**)&Wv_p,  g_Wv32);
    cudaGetSymbolAddress((void**)&Wo_p,  g_Wo32);
    cudaGetSymbolAddress((void**)&bqk_p, g_bqk);

    round_w<<<dim3(1024, 3), 256>>>(Wq, bq, Wk, bk, Wv, Wo);
    transpose_x<<<dim3(128, 16, 16), dim3(32, 8)>>>(x);

    // q/k projection: C[128 x 4096] per b (M=128 -> 128x128 kernel)
    gemm_proj<<<dim3(32, 1, NB), 256, PROJ_SMEM>>>(
        Wqk_p, 0, xT, (size_t)NHW * NC, bqk_p,
        qk_p, (size_t)128 * NHW, NHW);
    // v projection: C[512 x 4096] per b (big tiles)
    gemm_big<false><<<dim3(32, 2, NB), 256, BIG_SMEM>>>(
        Wv_p, 0, xT, (size_t)NHW * NC, bv,
        v_p, (size_t)NC * NHW, NHW);

    scores_kernel<<<128, 256>>>();
    attnv_tc<<<dim3(32, 8, NB), 256, ATTNV_SMEM>>>();

    // final linear: C[4096 x 512] per b (big tiles)
    gemm_big<true><<<dim3(4, 16, NB), 256, BIG_SMEM>>>(
        mid_p, (size_t)NC * NHW, Wo_p, 0, bo,
        out, (size_t)NC * NHW, NC);
}